// round 6
// baseline (speedup 1.0000x reference)
#include <cuda_runtime.h>
#include <cuda_bf16.h>
#include <math.h>
#include <float.h>
#include <stdint.h>

// Problem constants
#define Bsz 4
#define Sq  2048
#define Dm  1024
#define Hn  16
#define HD  64
#define MROWS (Bsz * Sq)          // 8192

typedef unsigned long long ull;
typedef __nv_bfloat16 bf16;

// ============================ PTX helpers ==================================
__device__ __forceinline__ uint32_t smem_u32(const void* p) {
    uint32_t a;
    asm("{ .reg .u64 t; cvta.to.shared.u64 t, %1; cvt.u32.u64 %0, t; }"
        : "=r"(a) : "l"(p));
    return a;
}
#define SWZ128(o) ((o) ^ (((o) >> 3) & 0x70))

__device__ __forceinline__ void cpa16(uint32_t saddr, const void* g) {
    asm volatile("cp.async.cg.shared.global [%0], [%1], 16;"
                 :: "r"(saddr), "l"(g) : "memory");
}
#define CP_COMMIT() asm volatile("cp.async.commit_group;" ::: "memory")
#define CP_WAIT1()  asm volatile("cp.async.wait_group 1;" ::: "memory")
#define CP_WAIT0()  asm volatile("cp.async.wait_group 0;" ::: "memory")

__device__ __forceinline__ void ldsm4(uint32_t* r, uint32_t addr) {
    asm volatile("ldmatrix.sync.aligned.m8n8.x4.shared.b16 {%0,%1,%2,%3}, [%4];"
                 : "=r"(r[0]), "=r"(r[1]), "=r"(r[2]), "=r"(r[3]) : "r"(addr));
}
__device__ __forceinline__ void ldsm4t(uint32_t* r, uint32_t addr) {
    asm volatile("ldmatrix.sync.aligned.m8n8.x4.trans.shared.b16 {%0,%1,%2,%3}, [%4];"
                 : "=r"(r[0]), "=r"(r[1]), "=r"(r[2]), "=r"(r[3]) : "r"(addr));
}
__device__ __forceinline__ void mma_bf16(float* d, const uint32_t* a, const uint32_t* b) {
    asm volatile(
        "mma.sync.aligned.m16n8k16.row.col.f32.bf16.bf16.f32 "
        "{%0,%1,%2,%3}, {%4,%5,%6,%7}, {%8,%9}, {%0,%1,%2,%3};"
        : "+f"(d[0]), "+f"(d[1]), "+f"(d[2]), "+f"(d[3])
        : "r"(a[0]), "r"(a[1]), "r"(a[2]), "r"(a[3]), "r"(b[0]), "r"(b[1]));
}
// pack two f32 -> bf16x2 register {lo, hi}
__device__ __forceinline__ uint32_t pk_bf16x2(float lo, float hi) {
    uint32_t r;
    asm("cvt.rn.bf16x2.f32 %0, %1, %2;" : "=r"(r) : "f"(hi), "f"(lo));
    return r;
}
__device__ __forceinline__ void upk_bf16x2(uint32_t v, float& lo, float& hi) {
    __nv_bfloat162 t = *reinterpret_cast<__nv_bfloat162*>(&v);
    lo = __bfloat162float(t.x); hi = __bfloat162float(t.y);
}

// ============================ scratch ======================================
__device__ bf16 g_Ahi[MROWS * Dm];
__device__ bf16 g_Alo[MROWS * Dm];
__device__ bf16 g_Wthi[Dm * Dm];
__device__ bf16 g_Wtlo[Dm * Dm];
__device__ bf16 g_Qh[MROWS * Dm];
__device__ bf16 g_Ql[MROWS * Dm];
__device__ bf16 g_Kh[MROWS * Dm];
__device__ bf16 g_Kl[MROWS * Dm];
__device__ bf16 g_Vh[MROWS * Dm];
__device__ bf16 g_Vl[MROWS * Dm];
__device__ bf16 g_Oh[MROWS * Dm];
__device__ bf16 g_Ol[MROWS * Dm];

// =================== split conversion: f32 -> bf16 hi/lo ===================
__device__ __forceinline__ void bsplit(float x, bf16 &h, bf16 &l) {
    h = __float2bfloat16(x);
    l = __float2bfloat16(x - __bfloat162float(h));
}

__global__ __launch_bounds__(256)
void fsplit(const float4* __restrict__ in, uint2* __restrict__ hi,
            uint2* __restrict__ lo, int n4)
{
    int i = blockIdx.x * 256 + threadIdx.x;
    if (i >= n4) return;
    float4 v = in[i];
    bf16 h0, h1, h2, h3, l0, l1, l2, l3;
    bsplit(v.x, h0, l0); bsplit(v.y, h1, l1);
    bsplit(v.z, h2, l2); bsplit(v.w, h3, l3);
    __nv_bfloat162 ph0 = __nv_bfloat162(h0, h1), ph1 = __nv_bfloat162(h2, h3);
    __nv_bfloat162 pl0 = __nv_bfloat162(l0, l1), pl1 = __nv_bfloat162(l2, l3);
    uint2 H, L;
    H.x = *(unsigned*)&ph0; H.y = *(unsigned*)&ph1;
    L.x = *(unsigned*)&pl0; L.y = *(unsigned*)&pl1;
    hi[i] = H; lo[i] = L;
}

// ========== transpose + split: W[K,N] f32 -> Wt[N,K] bf16 hi/lo ============
__global__ __launch_bounds__(256)
void wt_split(const float* __restrict__ W, bf16* __restrict__ Thi,
              bf16* __restrict__ Tlo)
{
    __shared__ float t[32][33];
    int n0 = blockIdx.x * 32, k0 = blockIdx.y * 32;
    int tx = threadIdx.x & 31, ty = threadIdx.x >> 5;   // 32 x 8
    #pragma unroll
    for (int i = 0; i < 4; i++)
        t[ty + 8 * i][tx] = W[(size_t)(k0 + ty + 8 * i) * Dm + n0 + tx];
    __syncthreads();
    #pragma unroll
    for (int i = 0; i < 4; i++) {
        float v = t[tx][ty + 8 * i];
        bf16 h, l; bsplit(v, h, l);
        size_t o = (size_t)(n0 + ty + 8 * i) * Dm + k0 + tx;
        Thi[o] = h; Tlo[o] = l;
    }
}

// ================== HMMA bf16-split GEMM + bias ===========================
// mode 0: write f32 to Cf.  mode 1: write bf16 hi/lo to Ch/Cl.
// Inner loop is TERM-MAJOR: all 16 accumulators between reuses of any one.
#define HBK 64
#define HBUF 65536
#define HSMEM (2 * HBUF)
#define HCHUNKS (Dm / HBK)

__global__ __launch_bounds__(256, 1)
void gemm_hmma(const bf16* __restrict__ Ahi, const bf16* __restrict__ Alo,
               const bf16* __restrict__ Bhi, const bf16* __restrict__ Blo,
               const float* __restrict__ bias,
               float* __restrict__ Cf, bf16* __restrict__ Ch,
               bf16* __restrict__ Cl, int mode)
{
    extern __shared__ __align__(1024) char smem[];
    const uint32_t sb = smem_u32(smem);

    const int tid  = threadIdx.x;
    const int wid  = tid >> 5;
    const int lane = tid & 31;
    const int wm   = wid & 3;
    const int wn   = wid >> 2;
    const int bm   = blockIdx.y * 128;
    const int bn   = blockIdx.x * 128;

    const int lrow = tid >> 3;
    const int lseg = tid & 7;

    float acc[2][8][4];
    #pragma unroll
    for (int fm = 0; fm < 2; fm++)
        #pragma unroll
        for (int fn = 0; fn < 8; fn++)
            #pragma unroll
            for (int e = 0; e < 4; e++) acc[fm][fn][e] = 0.0f;

    auto issue = [&](int c) {
        const uint32_t s0 = sb + (uint32_t)(c & 1) * HBUF;
        const size_t gofs = (size_t)c * HBK + lseg * 8;
        #pragma unroll
        for (int i = 0; i < 4; i++) {
            int row = lrow + i * 32;
            uint32_t so = SWZ128((uint32_t)(row * 128 + lseg * 16));
            cpa16(s0 + so,         Ahi + (size_t)(bm + row) * Dm + gofs);
            cpa16(s0 + 16384 + so, Alo + (size_t)(bm + row) * Dm + gofs);
            cpa16(s0 + 32768 + so, Bhi + (size_t)(bn + row) * Dm + gofs);
            cpa16(s0 + 49152 + so, Blo + (size_t)(bn + row) * Dm + gofs);
        }
    };

    const int a_row = wm * 32 + (lane & 15);
    const int a_sel = lane >> 4;
    const int b_row = wn * 64 + ((lane >> 4) << 3) + (lane & 7);
    const int b_sel = (lane >> 3) & 1;

    issue(0);
    CP_COMMIT();

    for (int c = 0; c < HCHUNKS; c++) {
        if (c + 1 < HCHUNKS) { issue(c + 1); CP_COMMIT(); CP_WAIT1(); }
        else { CP_COMMIT(); CP_WAIT0(); }
        __syncthreads();

        const uint32_t s0 = sb + (uint32_t)(c & 1) * HBUF;
        #pragma unroll
        for (int ks = 0; ks < 4; ks++) {
            uint32_t ah[2][4], al[2][4];
            #pragma unroll
            for (int fm = 0; fm < 2; fm++) {
                int row = a_row + fm * 16;
                int seg = 2 * ks + a_sel;
                uint32_t ad = s0 + SWZ128((uint32_t)(row * 128 + seg * 16));
                ldsm4(ah[fm], ad);
                ldsm4(al[fm], ad + 16384);
            }
            uint32_t bh[8][2], bl[8][2];
            #pragma unroll
            for (int f2 = 0; f2 < 4; f2++) {
                int row = b_row + f2 * 16;
                int seg = 2 * ks + b_sel;
                uint32_t bd = s0 + 32768 + SWZ128((uint32_t)(row * 128 + seg * 16));
                uint32_t t[4], u[4];
                ldsm4(t, bd);
                ldsm4(u, bd + 16384);
                bh[2*f2][0] = t[0]; bh[2*f2][1] = t[1];
                bh[2*f2+1][0] = t[2]; bh[2*f2+1][1] = t[3];
                bl[2*f2][0] = u[0]; bl[2*f2][1] = u[1];
                bl[2*f2+1][0] = u[2]; bl[2*f2+1][1] = u[3];
            }
            // term-major: 16 independent accumulators between same-acc reuse
            #pragma unroll
            for (int fm = 0; fm < 2; fm++)
                #pragma unroll
                for (int fn = 0; fn < 8; fn++)
                    mma_bf16(acc[fm][fn], ah[fm], bh[fn]);
            #pragma unroll
            for (int fm = 0; fm < 2; fm++)
                #pragma unroll
                for (int fn = 0; fn < 8; fn++)
                    mma_bf16(acc[fm][fn], ah[fm], bl[fn]);
            #pragma unroll
            for (int fm = 0; fm < 2; fm++)
                #pragma unroll
                for (int fn = 0; fn < 8; fn++)
                    mma_bf16(acc[fm][fn], al[fm], bh[fn]);
        }
        __syncthreads();
    }

    const int g  = lane >> 2;
    const int tq = lane & 3;
    #pragma unroll
    for (int fm = 0; fm < 2; fm++) {
        #pragma unroll
        for (int fn = 0; fn < 8; fn++) {
            int r0 = bm + wm * 32 + fm * 16 + g;
            int cc = bn + wn * 64 + fn * 8 + tq * 2;
            float b0 = bias[cc], b1 = bias[cc + 1];
            float v00 = acc[fm][fn][0] + b0, v01 = acc[fm][fn][1] + b1;
            float v10 = acc[fm][fn][2] + b0, v11 = acc[fm][fn][3] + b1;
            if (mode == 0) {
                *(float2*)(Cf + (size_t)r0 * Dm + cc) = make_float2(v00, v01);
                *(float2*)(Cf + (size_t)(r0 + 8) * Dm + cc) = make_float2(v10, v11);
            } else {
                uint32_t hp, lp; float hf0, hf1;
                hp = pk_bf16x2(v00, v01);
                upk_bf16x2(hp, hf0, hf1);
                lp = pk_bf16x2(v00 - hf0, v01 - hf1);
                *(uint32_t*)(Ch + (size_t)r0 * Dm + cc) = hp;
                *(uint32_t*)(Cl + (size_t)r0 * Dm + cc) = lp;
                hp = pk_bf16x2(v10, v11);
                upk_bf16x2(hp, hf0, hf1);
                lp = pk_bf16x2(v10 - hf0, v11 - hf1);
                *(uint32_t*)(Ch + (size_t)(r0 + 8) * Dm + cc) = hp;
                *(uint32_t*)(Cl + (size_t)(r0 + 8) * Dm + cc) = lp;
            }
        }
    }
}

// ---------------------------------------------------------------------------
// HMMA bf16-split flash attention. Term-major mma ordering throughout.
// Br=128 (8 warps x m16), Bc=128, HD=64.
// ---------------------------------------------------------------------------
#define AQ_OFF  0
#define AKV_OFF 32768
#define AKVBUF  65536
#define ATT_SMEM (AKV_OFF + 2 * AKVBUF)   // 163840
#define C2EXP 0.18033688011112042f        // 0.125 * log2(e)

__global__ __launch_bounds__(256, 1)
void attn_hmma(const bf16* __restrict__ Qh, const bf16* __restrict__ Ql,
               const bf16* __restrict__ Kh, const bf16* __restrict__ Kl,
               const bf16* __restrict__ Vh, const bf16* __restrict__ Vl,
               bf16* __restrict__ Oh, bf16* __restrict__ Ol)
{
    extern __shared__ __align__(1024) char smem[];
    const uint32_t sb = smem_u32(smem);

    const int tid  = threadIdx.x;
    const int wid  = tid >> 5;
    const int lane = tid & 31;
    const int g    = lane >> 2;
    const int tq   = lane & 3;

    const int bh = blockIdx.y;
    const int b  = bh >> 4;
    const int h  = bh & 15;
    const int q0 = blockIdx.x * 128;
    const size_t headoff = (size_t)(b * Sq) * Dm + h * HD;

    const int lr = tid >> 1;
    const int sh = (tid & 1) * 4;

    auto issueQ = [&]() {
        size_t gro = headoff + (size_t)(q0 + lr) * Dm;
        #pragma unroll
        for (int u = 0; u < 4; u++) {
            int seg = sh + u;
            uint32_t so = SWZ128((uint32_t)(lr * 128 + seg * 16));
            cpa16(sb + AQ_OFF + so,         Qh + gro + seg * 8);
            cpa16(sb + AQ_OFF + 16384 + so, Ql + gro + seg * 8);
        }
    };
    auto issueKV = [&](int t) {
        const uint32_t s0 = sb + AKV_OFF + (uint32_t)(t & 1) * AKVBUF;
        size_t gro = headoff + (size_t)(t * 128 + lr) * Dm;
        #pragma unroll
        for (int u = 0; u < 4; u++) {
            int seg = sh + u;
            uint32_t so = SWZ128((uint32_t)(lr * 128 + seg * 16));
            cpa16(s0 + so,         Kh + gro + seg * 8);
            cpa16(s0 + 16384 + so, Kl + gro + seg * 8);
            cpa16(s0 + 32768 + so, Vh + gro + seg * 8);
            cpa16(s0 + 49152 + so, Vl + gro + seg * 8);
        }
    };

    issueQ();  CP_COMMIT();
    issueKV(0); CP_COMMIT();
    CP_WAIT1();
    __syncthreads();

    uint32_t qh[4][4], ql[4][4];
    {
        int arow = wid * 16 + (lane & 15);
        int asel = lane >> 4;
        #pragma unroll
        for (int ks = 0; ks < 4; ks++) {
            uint32_t ad = sb + AQ_OFF + SWZ128((uint32_t)(arow * 128 + (2 * ks + asel) * 16));
            ldsm4(qh[ks], ad);
            ldsm4(ql[ks], ad + 16384);
        }
    }

    float o[8][4];
    #pragma unroll
    for (int fn = 0; fn < 8; fn++)
        #pragma unroll
        for (int e = 0; e < 4; e++) o[fn][e] = 0.0f;
    float m0 = -1e30f, m1 = -1e30f, l0 = 0.0f, l1 = 0.0f;

    const int kb_row = ((lane >> 4) << 3) + (lane & 7);
    const int kb_sel = (lane >> 3) & 1;
    const int vt_row = ((lane >> 3) & 1) * 8 + (lane & 7);
    const int vt_off = (lane >> 4) * 16;

    for (int t = 0; t < 16; t++) {
        __syncthreads();
        if (t + 1 < 16) { issueKV(t + 1); CP_COMMIT(); CP_WAIT1(); }
        else { CP_WAIT0(); }
        __syncthreads();

        const uint32_t s0 = sb + AKV_OFF + (uint32_t)(t & 1) * AKVBUF;

        // ---- S = Q K^T : term-major over ng-pairs (4 accs btwn reuse) ----
        float s[16][4];
        #pragma unroll
        for (int fn = 0; fn < 16; fn++)
            #pragma unroll
            for (int e = 0; e < 4; e++) s[fn][e] = 0.0f;

        #pragma unroll
        for (int ks = 0; ks < 4; ks++) {
            #pragma unroll
            for (int np = 0; np < 4; np++) {
                uint32_t kh0[4], kl0[4], kh1[4], kl1[4];
                uint32_t bd0 = s0 + SWZ128((uint32_t)(((2*np) * 16 + kb_row) * 128 +
                                                      (2 * ks + kb_sel) * 16));
                uint32_t bd1 = s0 + SWZ128((uint32_t)(((2*np+1) * 16 + kb_row) * 128 +
                                                      (2 * ks + kb_sel) * 16));
                ldsm4(kh0, bd0);
                ldsm4(kl0, bd0 + 16384);
                ldsm4(kh1, bd1);
                ldsm4(kl1, bd1 + 16384);
                float* sp = (float*)s[4*np];
                mma_bf16(sp + 0,  qh[ks], kh0);
                mma_bf16(sp + 4,  qh[ks], kh0 + 2);
                mma_bf16(sp + 8,  qh[ks], kh1);
                mma_bf16(sp + 12, qh[ks], kh1 + 2);
                mma_bf16(sp + 0,  qh[ks], kl0);
                mma_bf16(sp + 4,  qh[ks], kl0 + 2);
                mma_bf16(sp + 8,  qh[ks], kl1);
                mma_bf16(sp + 12, qh[ks], kl1 + 2);
                mma_bf16(sp + 0,  ql[ks], kh0);
                mma_bf16(sp + 4,  ql[ks], kh0 + 2);
                mma_bf16(sp + 8,  ql[ks], kh1);
                mma_bf16(sp + 12, ql[ks], kh1 + 2);
            }
        }

        // ---- online softmax ----
        float mx0 = -1e30f, mx1 = -1e30f;
        #pragma unroll
        for (int fn = 0; fn < 16; fn++) {
            mx0 = fmaxf(mx0, fmaxf(s[fn][0], s[fn][1]));
            mx1 = fmaxf(mx1, fmaxf(s[fn][2], s[fn][3]));
        }
        mx0 = fmaxf(mx0, __shfl_xor_sync(0xffffffffu, mx0, 1));
        mx0 = fmaxf(mx0, __shfl_xor_sync(0xffffffffu, mx0, 2));
        mx1 = fmaxf(mx1, __shfl_xor_sync(0xffffffffu, mx1, 1));
        mx1 = fmaxf(mx1, __shfl_xor_sync(0xffffffffu, mx1, 2));
        float nm0 = fmaxf(m0, mx0);
        float nm1 = fmaxf(m1, mx1);

        float sum0 = 0.0f, sum1 = 0.0f;
        #pragma unroll
        for (int fn = 0; fn < 16; fn++) {
            s[fn][0] = exp2f((s[fn][0] - nm0) * C2EXP);
            s[fn][1] = exp2f((s[fn][1] - nm0) * C2EXP);
            s[fn][2] = exp2f((s[fn][2] - nm1) * C2EXP);
            s[fn][3] = exp2f((s[fn][3] - nm1) * C2EXP);
            sum0 += s[fn][0] + s[fn][1];
            sum1 += s[fn][2] + s[fn][3];
        }
        sum0 += __shfl_xor_sync(0xffffffffu, sum0, 1);
        sum0 += __shfl_xor_sync(0xffffffffu, sum0, 2);
        sum1 += __shfl_xor_sync(0xffffffffu, sum1, 1);
        sum1 += __shfl_xor_sync(0xffffffffu, sum1, 2);

        float c0 = exp2f((m0 - nm0) * C2EXP);
        float c1 = exp2f((m1 - nm1) * C2EXP);
        l0 = l0 * c0 + sum0;  m0 = nm0;
        l1 = l1 * c1 + sum1;  m1 = nm1;
        #pragma unroll
        for (int fn = 0; fn < 8; fn++) {
            o[fn][0] *= c0; o[fn][1] *= c0;
            o[fn][2] *= c1; o[fn][3] *= c1;
        }

        // ---- O += P V : term-major over d-block pairs ----
        #pragma unroll
        for (int kc = 0; kc < 8; kc++) {
            uint32_t ah[4], al[4];
            #pragma unroll
            for (int q = 0; q < 4; q++) {
                const float* sv = s[2 * kc + (q >> 1)];
                float p0 = sv[(q & 1) * 2], p1 = sv[(q & 1) * 2 + 1];
                uint32_t hp = pk_bf16x2(p0, p1);
                float h0, h1; upk_bf16x2(hp, h0, h1);
                ah[q] = hp;
                al[q] = pk_bf16x2(p0 - h0, p1 - h1);
            }
            #pragma unroll
            for (int dp = 0; dp < 2; dp++) {
                int d0 = dp * 32;        // db = 2dp -> d0, db+1 -> d0+16
                uint32_t vd0 = s0 + 32768 +
                    SWZ128((uint32_t)((kc * 16 + vt_row) * 128 + d0 * 2 + vt_off));
                uint32_t vd1 = s0 + 32768 +
                    SWZ128((uint32_t)((kc * 16 + vt_row) * 128 + (d0 + 16) * 2 + vt_off));
                uint32_t vh0[4], vl0[4], vh1[4], vl1[4];
                ldsm4t(vh0, vd0);
                ldsm4t(vl0, vd0 + 16384);
                ldsm4t(vh1, vd1);
                ldsm4t(vl1, vd1 + 16384);
                float* op = (float*)o[4 * dp];
                mma_bf16(op + 0,  ah, vh0);
                mma_bf16(op + 4,  ah, vh0 + 2);
                mma_bf16(op + 8,  ah, vh1);
                mma_bf16(op + 12, ah, vh1 + 2);
                mma_bf16(op + 0,  ah, vl0);
                mma_bf16(op + 4,  ah, vl0 + 2);
                mma_bf16(op + 8,  ah, vl1);
                mma_bf16(op + 12, ah, vl1 + 2);
                mma_bf16(op + 0,  al, vh0);
                mma_bf16(op + 4,  al, vh0 + 2);
                mma_bf16(op + 8,  al, vh1);
                mma_bf16(op + 12, al, vh1 + 2);
            }
        }
    }

    // ---- normalize + store bf16 hi/lo ----
    float inv0 = 1.0f / l0, inv1 = 1.0f / l1;
    int r0 = q0 + wid * 16 + g;
    #pragma unroll
    for (int fn = 0; fn < 8; fn++) {
        int cc = fn * 8 + tq * 2;
        float v00 = o[fn][0] * inv0, v01 = o[fn][1] * inv0;
        float v10 = o[fn][2] * inv1, v11 = o[fn][3] * inv1;
        uint32_t hp, lp; float h0, h1;
        hp = pk_bf16x2(v00, v01);
        upk_bf16x2(hp, h0, h1);
        lp = pk_bf16x2(v00 - h0, v01 - h1);
        *(uint32_t*)(Oh + headoff + (size_t)r0 * Dm + cc) = hp;
        *(uint32_t*)(Ol + headoff + (size_t)r0 * Dm + cc) = lp;
        hp = pk_bf16x2(v10, v11);
        upk_bf16x2(hp, h0, h1);
        lp = pk_bf16x2(v10 - h0, v11 - h1);
        *(uint32_t*)(Oh + headoff + (size_t)(r0 + 8) * Dm + cc) = hp;
        *(uint32_t*)(Ol + headoff + (size_t)(r0 + 8) * Dm + cc) = lp;
    }
}

// ---------------------------------------------------------------------------
extern "C" void kernel_launch(void* const* d_in, const int* in_sizes, int n_in,
                              void* d_out, int out_size)
{
    const float* x  = (const float*)d_in[0];
    const float* wq = (const float*)d_in[1];
    const float* bq = (const float*)d_in[2];
    const float* wk = (const float*)d_in[3];
    const float* bk = (const float*)d_in[4];
    const float* wv = (const float*)d_in[5];
    const float* bv = (const float*)d_in[6];
    const float* wo = (const float*)d_in[7];
    const float* bo = (const float*)d_in[8];
    float* out = (float*)d_out;

    bf16 *ahi, *alo, *wthi, *wtlo;
    bf16 *qh, *ql, *kh, *kl, *vh, *vl, *oh, *ol;
    cudaGetSymbolAddress((void**)&ahi,  g_Ahi);
    cudaGetSymbolAddress((void**)&alo,  g_Alo);
    cudaGetSymbolAddress((void**)&wthi, g_Wthi);
    cudaGetSymbolAddress((void**)&wtlo, g_Wtlo);
    cudaGetSymbolAddress((void**)&qh,   g_Qh);
    cudaGetSymbolAddress((void**)&ql,   g_Ql);
    cudaGetSymbolAddress((void**)&kh,   g_Kh);
    cudaGetSymbolAddress((void**)&kl,   g_Kl);
    cudaGetSymbolAddress((void**)&vh,   g_Vh);
    cudaGetSymbolAddress((void**)&vl,   g_Vl);
    cudaGetSymbolAddress((void**)&oh,   g_Oh);
    cudaGetSymbolAddress((void**)&ol,   g_Ol);

    cudaFuncSetAttribute(gemm_hmma,
                         cudaFuncAttributeMaxDynamicSharedMemorySize, HSMEM);
    cudaFuncSetAttribute(attn_hmma,
                         cudaFuncAttributeMaxDynamicSharedMemorySize, ATT_SMEM);

    const int n4 = MROWS * Dm / 4;
    dim3 gt(Dm / 32, Dm / 32);
    dim3 gg(Dm / 128, MROWS / 128);   // (8, 64)

    fsplit<<<(n4 + 255) / 256, 256>>>((const float4*)x, (uint2*)ahi, (uint2*)alo, n4);

    wt_split<<<gt, 256>>>(wq, wthi, wtlo);
    gemm_hmma<<<gg, 256, HSMEM>>>(ahi, alo, wthi, wtlo, bq, nullptr, qh, ql, 1);
    wt_split<<<gt, 256>>>(wk, wthi, wtlo);
    gemm_hmma<<<gg, 256, HSMEM>>>(ahi, alo, wthi, wtlo, bk, nullptr, kh, kl, 1);
    wt_split<<<gt, 256>>>(wv, wthi, wtlo);
    gemm_hmma<<<gg, 256, HSMEM>>>(ahi, alo, wthi, wtlo, bv, nullptr, vh, vl, 1);

    dim3 ga(Sq / 128, Bsz * Hn);      // (16, 64)
    attn_hmma<<<ga, 256, ATT_SMEM>>>(qh, ql, kh, kl, vh, vl, oh, ol);

    wt_split<<<gt, 256>>>(wo, wthi, wtlo);
    gemm_hmma<<<gg, 256, HSMEM>>>(oh, ol, wthi, wtlo, bo, out, nullptr, nullptr, 0);
}

// round 7
// speedup vs baseline: 1.2211x; 1.2211x over previous
#include <cuda_runtime.h>
#include <cuda_fp16.h>
#include <math.h>
#include <float.h>
#include <stdint.h>

// Problem constants
#define Bsz 4
#define Sq  2048
#define Dm  1024
#define Hn  16
#define HD  64
#define MROWS (Bsz * Sq)          // 8192

typedef __half fp16;

// ============================ PTX helpers ==================================
__device__ __forceinline__ uint32_t smem_u32(const void* p) {
    uint32_t a;
    asm("{ .reg .u64 t; cvta.to.shared.u64 t, %1; cvt.u32.u64 %0, t; }"
        : "=r"(a) : "l"(p));
    return a;
}
#define SWZ128(o) ((o) ^ (((o) >> 3) & 0x70))

__device__ __forceinline__ void cpa16(uint32_t saddr, const void* g) {
    asm volatile("cp.async.cg.shared.global [%0], [%1], 16;"
                 :: "r"(saddr), "l"(g) : "memory");
}
#define CP_COMMIT() asm volatile("cp.async.commit_group;" ::: "memory")
#define CP_WAIT1()  asm volatile("cp.async.wait_group 1;" ::: "memory")
#define CP_WAIT0()  asm volatile("cp.async.wait_group 0;" ::: "memory")

__device__ __forceinline__ void ldsm4(uint32_t* r, uint32_t addr) {
    asm volatile("ldmatrix.sync.aligned.m8n8.x4.shared.b16 {%0,%1,%2,%3}, [%4];"
                 : "=r"(r[0]), "=r"(r[1]), "=r"(r[2]), "=r"(r[3]) : "r"(addr));
}
__device__ __forceinline__ void ldsm4t(uint32_t* r, uint32_t addr) {
    asm volatile("ldmatrix.sync.aligned.m8n8.x4.trans.shared.b16 {%0,%1,%2,%3}, [%4];"
                 : "=r"(r[0]), "=r"(r[1]), "=r"(r[2]), "=r"(r[3]) : "r"(addr));
}
__device__ __forceinline__ void mma_f16(float* d, const uint32_t* a, const uint32_t* b) {
    asm volatile(
        "mma.sync.aligned.m16n8k16.row.col.f32.f16.f16.f32 "
        "{%0,%1,%2,%3}, {%4,%5,%6,%7}, {%8,%9}, {%0,%1,%2,%3};"
        : "+f"(d[0]), "+f"(d[1]), "+f"(d[2]), "+f"(d[3])
        : "r"(a[0]), "r"(a[1]), "r"(a[2]), "r"(a[3]), "r"(b[0]), "r"(b[1]));
}
// pack two f32 -> fp16x2 register {x=lo, y=hi}
__device__ __forceinline__ uint32_t pk_f16x2(float lo, float hi) {
    __half2 t = __floats2half2_rn(lo, hi);
    return *reinterpret_cast<uint32_t*>(&t);
}
__device__ __forceinline__ void upk_f16x2(uint32_t v, float& lo, float& hi) {
    __half2 t = *reinterpret_cast<__half2*>(&v);
    float2 f = __half22float2(t);
    lo = f.x; hi = f.y;
}

// ============================ scratch ======================================
__device__ fp16 g_Ahi[MROWS * Dm];
__device__ fp16 g_Alo[MROWS * Dm];
__device__ fp16 g_Wthi[Dm * Dm];
__device__ fp16 g_Wtlo[Dm * Dm];
__device__ fp16 g_Qh[MROWS * Dm];
__device__ fp16 g_Ql[MROWS * Dm];
__device__ fp16 g_Kh[MROWS * Dm];
__device__ fp16 g_Kl[MROWS * Dm];
__device__ fp16 g_Vh[MROWS * Dm];
__device__ fp16 g_Oh[MROWS * Dm];
__device__ fp16 g_Ol[MROWS * Dm];

// =================== split conversion: f32 -> fp16 hi/lo ===================
__device__ __forceinline__ void hsplit(float x, fp16 &h, fp16 &l) {
    h = __float2half_rn(x);
    l = __float2half_rn(x - __half2float(h));
}

__global__ __launch_bounds__(256)
void fsplit(const float4* __restrict__ in, uint2* __restrict__ hi,
            uint2* __restrict__ lo, int n4)
{
    int i = blockIdx.x * 256 + threadIdx.x;
    if (i >= n4) return;
    float4 v = in[i];
    fp16 h0, h1, h2, h3, l0, l1, l2, l3;
    hsplit(v.x, h0, l0); hsplit(v.y, h1, l1);
    hsplit(v.z, h2, l2); hsplit(v.w, h3, l3);
    __half2 ph0 = __halves2half2(h0, h1), ph1 = __halves2half2(h2, h3);
    __half2 pl0 = __halves2half2(l0, l1), pl1 = __halves2half2(l2, l3);
    uint2 H, L;
    H.x = *(unsigned*)&ph0; H.y = *(unsigned*)&ph1;
    L.x = *(unsigned*)&pl0; L.y = *(unsigned*)&pl1;
    hi[i] = H; lo[i] = L;
}

// ====== transpose + split: W[K,N] f32 -> Wt[N,K] fp16 hi (+lo opt) =========
__global__ __launch_bounds__(256)
void wt_split(const float* __restrict__ W, fp16* __restrict__ Thi,
              fp16* __restrict__ Tlo)
{
    __shared__ float t[32][33];
    int n0 = blockIdx.x * 32, k0 = blockIdx.y * 32;
    int tx = threadIdx.x & 31, ty = threadIdx.x >> 5;   // 32 x 8
    #pragma unroll
    for (int i = 0; i < 4; i++)
        t[ty + 8 * i][tx] = W[(size_t)(k0 + ty + 8 * i) * Dm + n0 + tx];
    __syncthreads();
    #pragma unroll
    for (int i = 0; i < 4; i++) {
        float v = t[tx][ty + 8 * i];
        fp16 h, l; hsplit(v, h, l);
        size_t o = (size_t)(n0 + ty + 8 * i) * Dm + k0 + tx;
        Thi[o] = h;
        if (Tlo) Tlo[o] = l;
    }
}

// ================== HMMA fp16-split GEMM + bias ===========================
// nterms 3: Ah*Bh + Ah*Bl + Al*Bh.  nterms 2: Ah*Bh + Al*Bh (Blo unused).
// mode 0: f32 -> Cf.  mode 1: fp16 hi/lo -> Ch/Cl.  mode 2: fp16 -> Ch.
#define HBK 64
#define HBUF 65536
#define HSMEM (2 * HBUF)
#define HCHUNKS (Dm / HBK)

__global__ __launch_bounds__(256, 1)
void gemm_hmma(const fp16* __restrict__ Ahi, const fp16* __restrict__ Alo,
               const fp16* __restrict__ Bhi, const fp16* __restrict__ Blo,
               const float* __restrict__ bias,
               float* __restrict__ Cf, fp16* __restrict__ Ch,
               fp16* __restrict__ Cl, int mode, int nterms)
{
    extern __shared__ __align__(1024) char smem[];
    const uint32_t sb = smem_u32(smem);

    const int tid  = threadIdx.x;
    const int wid  = tid >> 5;
    const int lane = tid & 31;
    const int wm   = wid & 3;
    const int wn   = wid >> 2;
    const int bm   = blockIdx.y * 128;
    const int bn   = blockIdx.x * 128;

    const int lrow = tid >> 3;
    const int lseg = tid & 7;

    float acc[2][8][4];
    #pragma unroll
    for (int fm = 0; fm < 2; fm++)
        #pragma unroll
        for (int fn = 0; fn < 8; fn++)
            #pragma unroll
            for (int e = 0; e < 4; e++) acc[fm][fn][e] = 0.0f;

    auto issue = [&](int c) {
        const uint32_t s0 = sb + (uint32_t)(c & 1) * HBUF;
        const size_t gofs = (size_t)c * HBK + lseg * 8;
        #pragma unroll
        for (int i = 0; i < 4; i++) {
            int row = lrow + i * 32;
            uint32_t so = SWZ128((uint32_t)(row * 128 + lseg * 16));
            cpa16(s0 + so,         Ahi + (size_t)(bm + row) * Dm + gofs);
            cpa16(s0 + 16384 + so, Alo + (size_t)(bm + row) * Dm + gofs);
            cpa16(s0 + 32768 + so, Bhi + (size_t)(bn + row) * Dm + gofs);
            if (Blo)
                cpa16(s0 + 49152 + so, Blo + (size_t)(bn + row) * Dm + gofs);
        }
    };

    const int a_row = wm * 32 + (lane & 15);
    const int a_sel = lane >> 4;
    const int b_row = wn * 64 + ((lane >> 4) << 3) + (lane & 7);
    const int b_sel = (lane >> 3) & 1;

    issue(0);
    CP_COMMIT();

    for (int c = 0; c < HCHUNKS; c++) {
        if (c + 1 < HCHUNKS) { issue(c + 1); CP_COMMIT(); CP_WAIT1(); }
        else { CP_COMMIT(); CP_WAIT0(); }
        __syncthreads();

        const uint32_t s0 = sb + (uint32_t)(c & 1) * HBUF;
        #pragma unroll
        for (int ks = 0; ks < 4; ks++) {
            uint32_t ah[2][4], al[2][4];
            #pragma unroll
            for (int fm = 0; fm < 2; fm++) {
                int row = a_row + fm * 16;
                int seg = 2 * ks + a_sel;
                uint32_t ad = s0 + SWZ128((uint32_t)(row * 128 + seg * 16));
                ldsm4(ah[fm], ad);
                ldsm4(al[fm], ad + 16384);
            }
            uint32_t bh[8][2];
            #pragma unroll
            for (int f2 = 0; f2 < 4; f2++) {
                int row = b_row + f2 * 16;
                int seg = 2 * ks + b_sel;
                uint32_t bd = s0 + 32768 + SWZ128((uint32_t)(row * 128 + seg * 16));
                uint32_t t[4];
                ldsm4(t, bd);
                bh[2*f2][0] = t[0]; bh[2*f2][1] = t[1];
                bh[2*f2+1][0] = t[2]; bh[2*f2+1][1] = t[3];
            }
            #pragma unroll
            for (int fm = 0; fm < 2; fm++)
                #pragma unroll
                for (int fn = 0; fn < 8; fn++) {
                    mma_f16(acc[fm][fn], ah[fm], bh[fn]);
                    mma_f16(acc[fm][fn], al[fm], bh[fn]);
                }
            if (nterms == 3) {
                uint32_t bl[8][2];
                #pragma unroll
                for (int f2 = 0; f2 < 4; f2++) {
                    int row = b_row + f2 * 16;
                    int seg = 2 * ks + b_sel;
                    uint32_t bd = s0 + 49152 + SWZ128((uint32_t)(row * 128 + seg * 16));
                    uint32_t u[4];
                    ldsm4(u, bd);
                    bl[2*f2][0] = u[0]; bl[2*f2][1] = u[1];
                    bl[2*f2+1][0] = u[2]; bl[2*f2+1][1] = u[3];
                }
                #pragma unroll
                for (int fm = 0; fm < 2; fm++)
                    #pragma unroll
                    for (int fn = 0; fn < 8; fn++)
                        mma_f16(acc[fm][fn], ah[fm], bl[fn]);
            }
        }
        __syncthreads();
    }

    const int g  = lane >> 2;
    const int tq = lane & 3;
    #pragma unroll
    for (int fm = 0; fm < 2; fm++) {
        #pragma unroll
        for (int fn = 0; fn < 8; fn++) {
            int r0 = bm + wm * 32 + fm * 16 + g;
            int cc = bn + wn * 64 + fn * 8 + tq * 2;
            float b0 = bias[cc], b1 = bias[cc + 1];
            float v00 = acc[fm][fn][0] + b0, v01 = acc[fm][fn][1] + b1;
            float v10 = acc[fm][fn][2] + b0, v11 = acc[fm][fn][3] + b1;
            if (mode == 0) {
                *(float2*)(Cf + (size_t)r0 * Dm + cc) = make_float2(v00, v01);
                *(float2*)(Cf + (size_t)(r0 + 8) * Dm + cc) = make_float2(v10, v11);
            } else if (mode == 2) {
                *(uint32_t*)(Ch + (size_t)r0 * Dm + cc) = pk_f16x2(v00, v01);
                *(uint32_t*)(Ch + (size_t)(r0 + 8) * Dm + cc) = pk_f16x2(v10, v11);
            } else {
                uint32_t hp, lp; float hf0, hf1;
                hp = pk_f16x2(v00, v01);
                upk_f16x2(hp, hf0, hf1);
                lp = pk_f16x2(v00 - hf0, v01 - hf1);
                *(uint32_t*)(Ch + (size_t)r0 * Dm + cc) = hp;
                *(uint32_t*)(Cl + (size_t)r0 * Dm + cc) = lp;
                hp = pk_f16x2(v10, v11);
                upk_f16x2(hp, hf0, hf1);
                lp = pk_f16x2(v10 - hf0, v11 - hf1);
                *(uint32_t*)(Ch + (size_t)(r0 + 8) * Dm + cc) = hp;
                *(uint32_t*)(Cl + (size_t)(r0 + 8) * Dm + cc) = lp;
            }
        }
    }
}

// ---------------------------------------------------------------------------
// HMMA fp16 flash attention.  QK^T: 3-term split.  PV: plain fp16 (1-term).
// Br=128 (8 warps x m16), Bc=128. smem: Q 32KB + 2 x (Kh|Kl|V) 48KB = 128KB.
// ---------------------------------------------------------------------------
#define AQ_OFF  0
#define AKV_OFF 32768
#define AKVBUF  49152
#define ATT_SMEM (AKV_OFF + 2 * AKVBUF)   // 131072
#define C2EXP 0.18033688011112042f        // 0.125 * log2(e)

__global__ __launch_bounds__(256, 1)
void attn_hmma(const fp16* __restrict__ Qh, const fp16* __restrict__ Ql,
               const fp16* __restrict__ Kh, const fp16* __restrict__ Kl,
               const fp16* __restrict__ Vh,
               fp16* __restrict__ Oh, fp16* __restrict__ Ol)
{
    extern __shared__ __align__(1024) char smem[];
    const uint32_t sb = smem_u32(smem);

    const int tid  = threadIdx.x;
    const int wid  = tid >> 5;
    const int lane = tid & 31;
    const int g    = lane >> 2;
    const int tq   = lane & 3;

    const int bh = blockIdx.y;
    const int b  = bh >> 4;
    const int h  = bh & 15;
    const int q0 = blockIdx.x * 128;
    const size_t headoff = (size_t)(b * Sq) * Dm + h * HD;

    const int lr = tid >> 1;
    const int sh = (tid & 1) * 4;

    auto issueQ = [&]() {
        size_t gro = headoff + (size_t)(q0 + lr) * Dm;
        #pragma unroll
        for (int u = 0; u < 4; u++) {
            int seg = sh + u;
            uint32_t so = SWZ128((uint32_t)(lr * 128 + seg * 16));
            cpa16(sb + AQ_OFF + so,         Qh + gro + seg * 8);
            cpa16(sb + AQ_OFF + 16384 + so, Ql + gro + seg * 8);
        }
    };
    auto issueKV = [&](int t) {
        const uint32_t s0 = sb + AKV_OFF + (uint32_t)(t & 1) * AKVBUF;
        size_t gro = headoff + (size_t)(t * 128 + lr) * Dm;
        #pragma unroll
        for (int u = 0; u < 4; u++) {
            int seg = sh + u;
            uint32_t so = SWZ128((uint32_t)(lr * 128 + seg * 16));
            cpa16(s0 + so,         Kh + gro + seg * 8);
            cpa16(s0 + 16384 + so, Kl + gro + seg * 8);
            cpa16(s0 + 32768 + so, Vh + gro + seg * 8);
        }
    };

    issueQ();  CP_COMMIT();
    issueKV(0); CP_COMMIT();
    CP_WAIT1();
    __syncthreads();

    uint32_t qh[4][4], ql[4][4];
    {
        int arow = wid * 16 + (lane & 15);
        int asel = lane >> 4;
        #pragma unroll
        for (int ks = 0; ks < 4; ks++) {
            uint32_t ad = sb + AQ_OFF + SWZ128((uint32_t)(arow * 128 + (2 * ks + asel) * 16));
            ldsm4(qh[ks], ad);
            ldsm4(ql[ks], ad + 16384);
        }
    }

    float o[8][4];
    #pragma unroll
    for (int fn = 0; fn < 8; fn++)
        #pragma unroll
        for (int e = 0; e < 4; e++) o[fn][e] = 0.0f;
    float m0 = -1e30f, m1 = -1e30f, l0 = 0.0f, l1 = 0.0f;

    const int kb_row = ((lane >> 4) << 3) + (lane & 7);
    const int kb_sel = (lane >> 3) & 1;
    const int vt_row = ((lane >> 3) & 1) * 8 + (lane & 7);
    const int vt_off = (lane >> 4) * 16;

    for (int t = 0; t < 16; t++) {
        __syncthreads();
        if (t + 1 < 16) { issueKV(t + 1); CP_COMMIT(); CP_WAIT1(); }
        else { CP_WAIT0(); }
        __syncthreads();

        const uint32_t s0 = sb + AKV_OFF + (uint32_t)(t & 1) * AKVBUF;

        // ---- S = Q K^T : 3-term fp16 split ----
        float s[16][4];
        #pragma unroll
        for (int fn = 0; fn < 16; fn++)
            #pragma unroll
            for (int e = 0; e < 4; e++) s[fn][e] = 0.0f;

        #pragma unroll
        for (int ks = 0; ks < 4; ks++) {
            #pragma unroll
            for (int np = 0; np < 4; np++) {
                uint32_t kh0[4], kl0[4], kh1[4], kl1[4];
                uint32_t bd0 = s0 + SWZ128((uint32_t)(((2*np) * 16 + kb_row) * 128 +
                                                      (2 * ks + kb_sel) * 16));
                uint32_t bd1 = s0 + SWZ128((uint32_t)(((2*np+1) * 16 + kb_row) * 128 +
                                                      (2 * ks + kb_sel) * 16));
                ldsm4(kh0, bd0);
                ldsm4(kl0, bd0 + 16384);
                ldsm4(kh1, bd1);
                ldsm4(kl1, bd1 + 16384);
                float* sp = (float*)s[4*np];
                mma_f16(sp + 0,  qh[ks], kh0);
                mma_f16(sp + 4,  qh[ks], kh0 + 2);
                mma_f16(sp + 8,  qh[ks], kh1);
                mma_f16(sp + 12, qh[ks], kh1 + 2);
                mma_f16(sp + 0,  qh[ks], kl0);
                mma_f16(sp + 4,  qh[ks], kl0 + 2);
                mma_f16(sp + 8,  qh[ks], kl1);
                mma_f16(sp + 12, qh[ks], kl1 + 2);
                mma_f16(sp + 0,  ql[ks], kh0);
                mma_f16(sp + 4,  ql[ks], kh0 + 2);
                mma_f16(sp + 8,  ql[ks], kh1);
                mma_f16(sp + 12, ql[ks], kh1 + 2);
            }
        }

        // ---- online softmax ----
        float mx0 = -1e30f, mx1 = -1e30f;
        #pragma unroll
        for (int fn = 0; fn < 16; fn++) {
            mx0 = fmaxf(mx0, fmaxf(s[fn][0], s[fn][1]));
            mx1 = fmaxf(mx1, fmaxf(s[fn][2], s[fn][3]));
        }
        mx0 = fmaxf(mx0, __shfl_xor_sync(0xffffffffu, mx0, 1));
        mx0 = fmaxf(mx0, __shfl_xor_sync(0xffffffffu, mx0, 2));
        mx1 = fmaxf(mx1, __shfl_xor_sync(0xffffffffu, mx1, 1));
        mx1 = fmaxf(mx1, __shfl_xor_sync(0xffffffffu, mx1, 2));
        float nm0 = fmaxf(m0, mx0);
        float nm1 = fmaxf(m1, mx1);

        float sum0 = 0.0f, sum1 = 0.0f;
        #pragma unroll
        for (int fn = 0; fn < 16; fn++) {
            s[fn][0] = exp2f((s[fn][0] - nm0) * C2EXP);
            s[fn][1] = exp2f((s[fn][1] - nm0) * C2EXP);
            s[fn][2] = exp2f((s[fn][2] - nm1) * C2EXP);
            s[fn][3] = exp2f((s[fn][3] - nm1) * C2EXP);
            sum0 += s[fn][0] + s[fn][1];
            sum1 += s[fn][2] + s[fn][3];
        }
        sum0 += __shfl_xor_sync(0xffffffffu, sum0, 1);
        sum0 += __shfl_xor_sync(0xffffffffu, sum0, 2);
        sum1 += __shfl_xor_sync(0xffffffffu, sum1, 1);
        sum1 += __shfl_xor_sync(0xffffffffu, sum1, 2);

        float c0 = exp2f((m0 - nm0) * C2EXP);
        float c1 = exp2f((m1 - nm1) * C2EXP);
        l0 = l0 * c0 + sum0;  m0 = nm0;
        l1 = l1 * c1 + sum1;  m1 = nm1;
        #pragma unroll
        for (int fn = 0; fn < 8; fn++) {
            o[fn][0] *= c0; o[fn][1] *= c0;
            o[fn][2] *= c1; o[fn][3] *= c1;
        }

        // ---- O += P V : plain fp16 P, single V (1 term) ----
        #pragma unroll
        for (int kc = 0; kc < 8; kc++) {
            uint32_t ap[4];
            #pragma unroll
            for (int q = 0; q < 4; q++) {
                const float* sv = s[2 * kc + (q >> 1)];
                ap[q] = pk_f16x2(sv[(q & 1) * 2], sv[(q & 1) * 2 + 1]);
            }
            #pragma unroll
            for (int dp = 0; dp < 2; dp++) {
                int d0 = dp * 32;
                uint32_t vd0 = s0 + 32768 +
                    SWZ128((uint32_t)((kc * 16 + vt_row) * 128 + d0 * 2 + vt_off));
                uint32_t vd1 = s0 + 32768 +
                    SWZ128((uint32_t)((kc * 16 + vt_row) * 128 + (d0 + 16) * 2 + vt_off));
                uint32_t vh0[4], vh1[4];
                ldsm4t(vh0, vd0);
                ldsm4t(vh1, vd1);
                float* op = (float*)o[4 * dp];
                mma_f16(op + 0,  ap, vh0);
                mma_f16(op + 4,  ap, vh0 + 2);
                mma_f16(op + 8,  ap, vh1);
                mma_f16(op + 12, ap, vh1 + 2);
            }
        }
    }

    // ---- normalize + store fp16 hi/lo ----
    float inv0 = 1.0f / l0, inv1 = 1.0f / l1;
    int r0 = q0 + wid * 16 + g;
    #pragma unroll
    for (int fn = 0; fn < 8; fn++) {
        int cc = fn * 8 + tq * 2;
        float v00 = o[fn][0] * inv0, v01 = o[fn][1] * inv0;
        float v10 = o[fn][2] * inv1, v11 = o[fn][3] * inv1;
        uint32_t hp, lp; float h0, h1;
        hp = pk_f16x2(v00, v01);
        upk_f16x2(hp, h0, h1);
        lp = pk_f16x2(v00 - h0, v01 - h1);
        *(uint32_t*)(Oh + headoff + (size_t)r0 * Dm + cc) = hp;
        *(uint32_t*)(Ol + headoff + (size_t)r0 * Dm + cc) = lp;
        hp = pk_f16x2(v10, v11);
        upk_f16x2(hp, h0, h1);
        lp = pk_f16x2(v10 - h0, v11 - h1);
        *(uint32_t*)(Oh + headoff + (size_t)(r0 + 8) * Dm + cc) = hp;
        *(uint32_t*)(Ol + headoff + (size_t)(r0 + 8) * Dm + cc) = lp;
    }
}

// ---------------------------------------------------------------------------
extern "C" void kernel_launch(void* const* d_in, const int* in_sizes, int n_in,
                              void* d_out, int out_size)
{
    const float* x  = (const float*)d_in[0];
    const float* wq = (const float*)d_in[1];
    const float* bq = (const float*)d_in[2];
    const float* wk = (const float*)d_in[3];
    const float* bk = (const float*)d_in[4];
    const float* wv = (const float*)d_in[5];
    const float* bv = (const float*)d_in[6];
    const float* wo = (const float*)d_in[7];
    const float* bo = (const float*)d_in[8];
    float* out = (float*)d_out;

    fp16 *ahi, *alo, *wthi, *wtlo;
    fp16 *qh, *ql, *kh, *kl, *vh, *oh, *ol;
    cudaGetSymbolAddress((void**)&ahi,  g_Ahi);
    cudaGetSymbolAddress((void**)&alo,  g_Alo);
    cudaGetSymbolAddress((void**)&wthi, g_Wthi);
    cudaGetSymbolAddress((void**)&wtlo, g_Wtlo);
    cudaGetSymbolAddress((void**)&qh,   g_Qh);
    cudaGetSymbolAddress((void**)&ql,   g_Ql);
    cudaGetSymbolAddress((void**)&kh,   g_Kh);
    cudaGetSymbolAddress((void**)&kl,   g_Kl);
    cudaGetSymbolAddress((void**)&vh,   g_Vh);
    cudaGetSymbolAddress((void**)&oh,   g_Oh);
    cudaGetSymbolAddress((void**)&ol,   g_Ol);

    cudaFuncSetAttribute(gemm_hmma,
                         cudaFuncAttributeMaxDynamicSharedMemorySize, HSMEM);
    cudaFuncSetAttribute(attn_hmma,
                         cudaFuncAttributeMaxDynamicSharedMemorySize, ATT_SMEM);

    const int n4 = MROWS * Dm / 4;
    dim3 gt(Dm / 32, Dm / 32);
    dim3 gg(Dm / 128, MROWS / 128);   // (8, 64)

    fsplit<<<(n4 + 255) / 256, 256>>>((const float4*)x, (uint2*)ahi, (uint2*)alo, n4);

    // Q, K: 3-term (feeds exp-amplified path)
    wt_split<<<gt, 256>>>(wq, wthi, wtlo);
    gemm_hmma<<<gg, 256, HSMEM>>>(ahi, alo, wthi, wtlo, bq, nullptr, qh, ql, 1, 3);
    wt_split<<<gt, 256>>>(wk, wthi, wtlo);
    gemm_hmma<<<gg, 256, HSMEM>>>(ahi, alo, wthi, wtlo, bk, nullptr, kh, kl, 1, 3);
    // V: 3-term, single-fp16 output
    wt_split<<<gt, 256>>>(wv, wthi, wtlo);
    gemm_hmma<<<gg, 256, HSMEM>>>(ahi, alo, wthi, wtlo, bv, nullptr, vh, nullptr, 2, 3);

    dim3 ga(Sq / 128, Bsz * Hn);      // (16, 64)
    attn_hmma<<<ga, 256, ATT_SMEM>>>(qh, ql, kh, kl, vh, oh, ol);

    // O-projection: 2-term (Wo hi only), f32 output
    wt_split<<<gt, 256>>>(wo, wthi, nullptr);
    gemm_hmma<<<gg, 256, HSMEM>>>(oh, ol, wthi, nullptr, bo, out, nullptr, nullptr, 0, 2);
}

// round 8
// speedup vs baseline: 1.4818x; 1.2136x over previous
#include <cuda_runtime.h>
#include <cuda_fp16.h>
#include <math.h>
#include <float.h>
#include <stdint.h>

// Problem constants
#define Bsz 4
#define Sq  2048
#define Dm  1024
#define Hn  16
#define HD  64
#define MROWS (Bsz * Sq)          // 8192

typedef __half fp16;

// ============================ PTX helpers ==================================
__device__ __forceinline__ uint32_t smem_u32(const void* p) {
    uint32_t a;
    asm("{ .reg .u64 t; cvta.to.shared.u64 t, %1; cvt.u32.u64 %0, t; }"
        : "=r"(a) : "l"(p));
    return a;
}
#define SWZ128(o) ((o) ^ (((o) >> 3) & 0x70))

__device__ __forceinline__ void cpa16(uint32_t saddr, const void* g) {
    asm volatile("cp.async.cg.shared.global [%0], [%1], 16;"
                 :: "r"(saddr), "l"(g) : "memory");
}
#define CP_COMMIT() asm volatile("cp.async.commit_group;" ::: "memory")
#define CP_WAIT1()  asm volatile("cp.async.wait_group 1;" ::: "memory")
#define CP_WAIT0()  asm volatile("cp.async.wait_group 0;" ::: "memory")

__device__ __forceinline__ void ldsm4(uint32_t* r, uint32_t addr) {
    asm volatile("ldmatrix.sync.aligned.m8n8.x4.shared.b16 {%0,%1,%2,%3}, [%4];"
                 : "=r"(r[0]), "=r"(r[1]), "=r"(r[2]), "=r"(r[3]) : "r"(addr));
}
__device__ __forceinline__ void ldsm4t(uint32_t* r, uint32_t addr) {
    asm volatile("ldmatrix.sync.aligned.m8n8.x4.trans.shared.b16 {%0,%1,%2,%3}, [%4];"
                 : "=r"(r[0]), "=r"(r[1]), "=r"(r[2]), "=r"(r[3]) : "r"(addr));
}
__device__ __forceinline__ void mma_f16(float* d, const uint32_t* a, const uint32_t* b) {
    asm volatile(
        "mma.sync.aligned.m16n8k16.row.col.f32.f16.f16.f32 "
        "{%0,%1,%2,%3}, {%4,%5,%6,%7}, {%8,%9}, {%0,%1,%2,%3};"
        : "+f"(d[0]), "+f"(d[1]), "+f"(d[2]), "+f"(d[3])
        : "r"(a[0]), "r"(a[1]), "r"(a[2]), "r"(a[3]), "r"(b[0]), "r"(b[1]));
}
__device__ __forceinline__ uint32_t pk_f16x2(float lo, float hi) {
    __half2 t = __floats2half2_rn(lo, hi);
    return *reinterpret_cast<uint32_t*>(&t);
}
__device__ __forceinline__ void upk_f16x2(uint32_t v, float& lo, float& hi) {
    __half2 t = *reinterpret_cast<__half2*>(&v);
    float2 f = __half22float2(t);
    lo = f.x; hi = f.y;
}

// ============================ scratch ======================================
__device__ fp16 g_Ahi[MROWS * Dm];
__device__ fp16 g_Alo[MROWS * Dm];
__device__ fp16 g_Wthi[Dm * Dm];
__device__ fp16 g_Qh[MROWS * Dm];
__device__ fp16 g_Kh[MROWS * Dm];
__device__ fp16 g_Kl[MROWS * Dm];
__device__ fp16 g_Vh[MROWS * Dm];
__device__ fp16 g_Oh[MROWS * Dm];
__device__ fp16 g_Ol[MROWS * Dm];

// =================== split conversion: f32 -> fp16 hi/lo ===================
__device__ __forceinline__ void hsplit(float x, fp16 &h, fp16 &l) {
    h = __float2half_rn(x);
    l = __float2half_rn(x - __half2float(h));
}

__global__ __launch_bounds__(256)
void fsplit(const float4* __restrict__ in, uint2* __restrict__ hi,
            uint2* __restrict__ lo, int n4)
{
    int i = blockIdx.x * 256 + threadIdx.x;
    if (i >= n4) return;
    float4 v = in[i];
    fp16 h0, h1, h2, h3, l0, l1, l2, l3;
    hsplit(v.x, h0, l0); hsplit(v.y, h1, l1);
    hsplit(v.z, h2, l2); hsplit(v.w, h3, l3);
    __half2 ph0 = __halves2half2(h0, h1), ph1 = __halves2half2(h2, h3);
    __half2 pl0 = __halves2half2(l0, l1), pl1 = __halves2half2(l2, l3);
    uint2 H, L;
    H.x = *(unsigned*)&ph0; H.y = *(unsigned*)&ph1;
    L.x = *(unsigned*)&pl0; L.y = *(unsigned*)&pl1;
    hi[i] = H; lo[i] = L;
}

// ====== transpose: W[K,N] f32 -> Wt[N,K] fp16 (hi only) ====================
__global__ __launch_bounds__(256)
void wt_split(const float* __restrict__ W, fp16* __restrict__ Thi)
{
    __shared__ float t[32][33];
    int n0 = blockIdx.x * 32, k0 = blockIdx.y * 32;
    int tx = threadIdx.x & 31, ty = threadIdx.x >> 5;   // 32 x 8
    #pragma unroll
    for (int i = 0; i < 4; i++)
        t[ty + 8 * i][tx] = W[(size_t)(k0 + ty + 8 * i) * Dm + n0 + tx];
    __syncthreads();
    #pragma unroll
    for (int i = 0; i < 4; i++) {
        float v = t[tx][ty + 8 * i];
        size_t o = (size_t)(n0 + ty + 8 * i) * Dm + k0 + tx;
        Thi[o] = __float2half_rn(v);
    }
}

// ================== HMMA fp16 2-term GEMM + bias ==========================
// C = (Ah + Al) @ Bh^T + bias.
// mode 0: f32 -> Cf.  mode 1: fp16 hi/lo -> Ch/Cl.  mode 2: fp16 -> Ch.
#define HBK 64
#define HBUF 49152                 // Ah 16K | Al 16K | Bh 16K
#define HSMEM (2 * HBUF)           // 96KB
#define HCHUNKS (Dm / HBK)

__global__ __launch_bounds__(256, 1)
void gemm_hmma(const fp16* __restrict__ Ahi, const fp16* __restrict__ Alo,
               const fp16* __restrict__ Bhi,
               const float* __restrict__ bias,
               float* __restrict__ Cf, fp16* __restrict__ Ch,
               fp16* __restrict__ Cl, int mode)
{
    extern __shared__ __align__(1024) char smem[];
    const uint32_t sb = smem_u32(smem);

    const int tid  = threadIdx.x;
    const int wid  = tid >> 5;
    const int lane = tid & 31;
    const int wm   = wid & 3;
    const int wn   = wid >> 2;
    const int bm   = blockIdx.y * 128;
    const int bn   = blockIdx.x * 128;

    const int lrow = tid >> 3;
    const int lseg = tid & 7;

    float acc[2][8][4];
    #pragma unroll
    for (int fm = 0; fm < 2; fm++)
        #pragma unroll
        for (int fn = 0; fn < 8; fn++)
            #pragma unroll
            for (int e = 0; e < 4; e++) acc[fm][fn][e] = 0.0f;

    auto issue = [&](int c) {
        const uint32_t s0 = sb + (uint32_t)(c & 1) * HBUF;
        const size_t gofs = (size_t)c * HBK + lseg * 8;
        #pragma unroll
        for (int i = 0; i < 4; i++) {
            int row = lrow + i * 32;
            uint32_t so = SWZ128((uint32_t)(row * 128 + lseg * 16));
            cpa16(s0 + so,         Ahi + (size_t)(bm + row) * Dm + gofs);
            cpa16(s0 + 16384 + so, Alo + (size_t)(bm + row) * Dm + gofs);
            cpa16(s0 + 32768 + so, Bhi + (size_t)(bn + row) * Dm + gofs);
        }
    };

    const int a_row = wm * 32 + (lane & 15);
    const int a_sel = lane >> 4;
    const int b_row = wn * 64 + ((lane >> 4) << 3) + (lane & 7);
    const int b_sel = (lane >> 3) & 1;

    issue(0);
    CP_COMMIT();

    for (int c = 0; c < HCHUNKS; c++) {
        if (c + 1 < HCHUNKS) { issue(c + 1); CP_COMMIT(); CP_WAIT1(); }
        else { CP_COMMIT(); CP_WAIT0(); }
        __syncthreads();

        const uint32_t s0 = sb + (uint32_t)(c & 1) * HBUF;
        #pragma unroll
        for (int ks = 0; ks < 4; ks++) {
            uint32_t ah[2][4], al[2][4];
            #pragma unroll
            for (int fm = 0; fm < 2; fm++) {
                int row = a_row + fm * 16;
                int seg = 2 * ks + a_sel;
                uint32_t ad = s0 + SWZ128((uint32_t)(row * 128 + seg * 16));
                ldsm4(ah[fm], ad);
                ldsm4(al[fm], ad + 16384);
            }
            uint32_t bh[8][2];
            #pragma unroll
            for (int f2 = 0; f2 < 4; f2++) {
                int row = b_row + f2 * 16;
                int seg = 2 * ks + b_sel;
                uint32_t bd = s0 + 32768 + SWZ128((uint32_t)(row * 128 + seg * 16));
                uint32_t t[4];
                ldsm4(t, bd);
                bh[2*f2][0] = t[0]; bh[2*f2][1] = t[1];
                bh[2*f2+1][0] = t[2]; bh[2*f2+1][1] = t[3];
            }
            #pragma unroll
            for (int fm = 0; fm < 2; fm++)
                #pragma unroll
                for (int fn = 0; fn < 8; fn++) {
                    mma_f16(acc[fm][fn], ah[fm], bh[fn]);
                    mma_f16(acc[fm][fn], al[fm], bh[fn]);
                }
        }
        __syncthreads();
    }

    const int g  = lane >> 2;
    const int tq = lane & 3;
    #pragma unroll
    for (int fm = 0; fm < 2; fm++) {
        #pragma unroll
        for (int fn = 0; fn < 8; fn++) {
            int r0 = bm + wm * 32 + fm * 16 + g;
            int cc = bn + wn * 64 + fn * 8 + tq * 2;
            float b0 = bias[cc], b1 = bias[cc + 1];
            float v00 = acc[fm][fn][0] + b0, v01 = acc[fm][fn][1] + b1;
            float v10 = acc[fm][fn][2] + b0, v11 = acc[fm][fn][3] + b1;
            if (mode == 0) {
                *(float2*)(Cf + (size_t)r0 * Dm + cc) = make_float2(v00, v01);
                *(float2*)(Cf + (size_t)(r0 + 8) * Dm + cc) = make_float2(v10, v11);
            } else if (mode == 2) {
                *(uint32_t*)(Ch + (size_t)r0 * Dm + cc) = pk_f16x2(v00, v01);
                *(uint32_t*)(Ch + (size_t)(r0 + 8) * Dm + cc) = pk_f16x2(v10, v11);
            } else {
                uint32_t hp, lp; float hf0, hf1;
                hp = pk_f16x2(v00, v01);
                upk_f16x2(hp, hf0, hf1);
                lp = pk_f16x2(v00 - hf0, v01 - hf1);
                *(uint32_t*)(Ch + (size_t)r0 * Dm + cc) = hp;
                *(uint32_t*)(Cl + (size_t)r0 * Dm + cc) = lp;
                hp = pk_f16x2(v10, v11);
                upk_f16x2(hp, hf0, hf1);
                lp = pk_f16x2(v10 - hf0, v11 - hf1);
                *(uint32_t*)(Ch + (size_t)(r0 + 8) * Dm + cc) = hp;
                *(uint32_t*)(Cl + (size_t)(r0 + 8) * Dm + cc) = lp;
            }
        }
    }
}

// ---------------------------------------------------------------------------
// HMMA fp16 flash attention.
// QK^T: 2-term  S = Qh*(Kh + Kl).   PV: plain fp16 (1 term).
// Br=128 (8 warps x m16), Bc=128.
// smem: Q 16KB + 2 x (Kh|Kl|V) 48KB = 112KB.
// ---------------------------------------------------------------------------
#define AQ_OFF  0
#define AKV_OFF 16384
#define AKVBUF  49152
#define ATT_SMEM (AKV_OFF + 2 * AKVBUF)   // 114688
#define C2EXP 0.18033688011112042f        // 0.125 * log2(e)

__global__ __launch_bounds__(256, 1)
void attn_hmma(const fp16* __restrict__ Qh,
               const fp16* __restrict__ Kh, const fp16* __restrict__ Kl,
               const fp16* __restrict__ Vh,
               fp16* __restrict__ Oh, fp16* __restrict__ Ol)
{
    extern __shared__ __align__(1024) char smem[];
    const uint32_t sb = smem_u32(smem);

    const int tid  = threadIdx.x;
    const int wid  = tid >> 5;
    const int lane = tid & 31;
    const int g    = lane >> 2;
    const int tq   = lane & 3;

    const int bh = blockIdx.y;
    const int b  = bh >> 4;
    const int h  = bh & 15;
    const int q0 = blockIdx.x * 128;
    const size_t headoff = (size_t)(b * Sq) * Dm + h * HD;

    const int lr = tid >> 1;
    const int sh = (tid & 1) * 4;

    auto issueQ = [&]() {
        size_t gro = headoff + (size_t)(q0 + lr) * Dm;
        #pragma unroll
        for (int u = 0; u < 4; u++) {
            int seg = sh + u;
            uint32_t so = SWZ128((uint32_t)(lr * 128 + seg * 16));
            cpa16(sb + AQ_OFF + so, Qh + gro + seg * 8);
        }
    };
    auto issueKV = [&](int t) {
        const uint32_t s0 = sb + AKV_OFF + (uint32_t)(t & 1) * AKVBUF;
        size_t gro = headoff + (size_t)(t * 128 + lr) * Dm;
        #pragma unroll
        for (int u = 0; u < 4; u++) {
            int seg = sh + u;
            uint32_t so = SWZ128((uint32_t)(lr * 128 + seg * 16));
            cpa16(s0 + so,         Kh + gro + seg * 8);
            cpa16(s0 + 16384 + so, Kl + gro + seg * 8);
            cpa16(s0 + 32768 + so, Vh + gro + seg * 8);
        }
    };

    issueQ();  CP_COMMIT();
    issueKV(0); CP_COMMIT();
    CP_WAIT1();
    __syncthreads();

    uint32_t qh[4][4];
    {
        int arow = wid * 16 + (lane & 15);
        int asel = lane >> 4;
        #pragma unroll
        for (int ks = 0; ks < 4; ks++) {
            uint32_t ad = sb + AQ_OFF + SWZ128((uint32_t)(arow * 128 + (2 * ks + asel) * 16));
            ldsm4(qh[ks], ad);
        }
    }

    float o[8][4];
    #pragma unroll
    for (int fn = 0; fn < 8; fn++)
        #pragma unroll
        for (int e = 0; e < 4; e++) o[fn][e] = 0.0f;
    float m0 = -1e30f, m1 = -1e30f, l0 = 0.0f, l1 = 0.0f;

    const int kb_row = ((lane >> 4) << 3) + (lane & 7);
    const int kb_sel = (lane >> 3) & 1;
    const int vt_row = ((lane >> 3) & 1) * 8 + (lane & 7);
    const int vt_off = (lane >> 4) * 16;

    for (int t = 0; t < 16; t++) {
        __syncthreads();
        if (t + 1 < 16) { issueKV(t + 1); CP_COMMIT(); CP_WAIT1(); }
        else { CP_WAIT0(); }
        __syncthreads();

        const uint32_t s0 = sb + AKV_OFF + (uint32_t)(t & 1) * AKVBUF;

        // ---- S = Qh (Kh + Kl) : 2-term fp16 ----
        float s[16][4];
        #pragma unroll
        for (int fn = 0; fn < 16; fn++)
            #pragma unroll
            for (int e = 0; e < 4; e++) s[fn][e] = 0.0f;

        #pragma unroll
        for (int ks = 0; ks < 4; ks++) {
            #pragma unroll
            for (int np = 0; np < 4; np++) {
                uint32_t kh0[4], kl0[4], kh1[4], kl1[4];
                uint32_t bd0 = s0 + SWZ128((uint32_t)(((2*np) * 16 + kb_row) * 128 +
                                                      (2 * ks + kb_sel) * 16));
                uint32_t bd1 = s0 + SWZ128((uint32_t)(((2*np+1) * 16 + kb_row) * 128 +
                                                      (2 * ks + kb_sel) * 16));
                ldsm4(kh0, bd0);
                ldsm4(kl0, bd0 + 16384);
                ldsm4(kh1, bd1);
                ldsm4(kl1, bd1 + 16384);
                float* sp = (float*)s[4*np];
                mma_f16(sp + 0,  qh[ks], kh0);
                mma_f16(sp + 4,  qh[ks], kh0 + 2);
                mma_f16(sp + 8,  qh[ks], kh1);
                mma_f16(sp + 12, qh[ks], kh1 + 2);
                mma_f16(sp + 0,  qh[ks], kl0);
                mma_f16(sp + 4,  qh[ks], kl0 + 2);
                mma_f16(sp + 8,  qh[ks], kl1);
                mma_f16(sp + 12, qh[ks], kl1 + 2);
            }
        }

        // ---- online softmax ----
        float mx0 = -1e30f, mx1 = -1e30f;
        #pragma unroll
        for (int fn = 0; fn < 16; fn++) {
            mx0 = fmaxf(mx0, fmaxf(s[fn][0], s[fn][1]));
            mx1 = fmaxf(mx1, fmaxf(s[fn][2], s[fn][3]));
        }
        mx0 = fmaxf(mx0, __shfl_xor_sync(0xffffffffu, mx0, 1));
        mx0 = fmaxf(mx0, __shfl_xor_sync(0xffffffffu, mx0, 2));
        mx1 = fmaxf(mx1, __shfl_xor_sync(0xffffffffu, mx1, 1));
        mx1 = fmaxf(mx1, __shfl_xor_sync(0xffffffffu, mx1, 2));
        float nm0 = fmaxf(m0, mx0);
        float nm1 = fmaxf(m1, mx1);

        float sum0 = 0.0f, sum1 = 0.0f;
        #pragma unroll
        for (int fn = 0; fn < 16; fn++) {
            s[fn][0] = exp2f((s[fn][0] - nm0) * C2EXP);
            s[fn][1] = exp2f((s[fn][1] - nm0) * C2EXP);
            s[fn][2] = exp2f((s[fn][2] - nm1) * C2EXP);
            s[fn][3] = exp2f((s[fn][3] - nm1) * C2EXP);
            sum0 += s[fn][0] + s[fn][1];
            sum1 += s[fn][2] + s[fn][3];
        }
        sum0 += __shfl_xor_sync(0xffffffffu, sum0, 1);
        sum0 += __shfl_xor_sync(0xffffffffu, sum0, 2);
        sum1 += __shfl_xor_sync(0xffffffffu, sum1, 1);
        sum1 += __shfl_xor_sync(0xffffffffu, sum1, 2);

        float c0 = exp2f((m0 - nm0) * C2EXP);
        float c1 = exp2f((m1 - nm1) * C2EXP);
        l0 = l0 * c0 + sum0;  m0 = nm0;
        l1 = l1 * c1 + sum1;  m1 = nm1;
        #pragma unroll
        for (int fn = 0; fn < 8; fn++) {
            o[fn][0] *= c0; o[fn][1] *= c0;
            o[fn][2] *= c1; o[fn][3] *= c1;
        }

        // ---- O += P V : plain fp16 P, single V ----
        #pragma unroll
        for (int kc = 0; kc < 8; kc++) {
            uint32_t ap[4];
            #pragma unroll
            for (int q = 0; q < 4; q++) {
                const float* sv = s[2 * kc + (q >> 1)];
                ap[q] = pk_f16x2(sv[(q & 1) * 2], sv[(q & 1) * 2 + 1]);
            }
            #pragma unroll
            for (int dp = 0; dp < 2; dp++) {
                int d0 = dp * 32;
                uint32_t vd0 = s0 + 32768 +
                    SWZ128((uint32_t)((kc * 16 + vt_row) * 128 + d0 * 2 + vt_off));
                uint32_t vd1 = s0 + 32768 +
                    SWZ128((uint32_t)((kc * 16 + vt_row) * 128 + (d0 + 16) * 2 + vt_off));
                uint32_t vh0[4], vh1[4];
                ldsm4t(vh0, vd0);
                ldsm4t(vh1, vd1);
                float* op = (float*)o[4 * dp];
                mma_f16(op + 0,  ap, vh0);
                mma_f16(op + 4,  ap, vh0 + 2);
                mma_f16(op + 8,  ap, vh1);
                mma_f16(op + 12, ap, vh1 + 2);
            }
        }
    }

    // ---- normalize + store fp16 hi/lo ----
    float inv0 = 1.0f / l0, inv1 = 1.0f / l1;
    int r0 = q0 + wid * 16 + g;
    #pragma unroll
    for (int fn = 0; fn < 8; fn++) {
        int cc = fn * 8 + tq * 2;
        float v00 = o[fn][0] * inv0, v01 = o[fn][1] * inv0;
        float v10 = o[fn][2] * inv1, v11 = o[fn][3] * inv1;
        uint32_t hp, lp; float h0, h1;
        hp = pk_f16x2(v00, v01);
        upk_f16x2(hp, h0, h1);
        lp = pk_f16x2(v00 - h0, v01 - h1);
        *(uint32_t*)(Oh + headoff + (size_t)r0 * Dm + cc) = hp;
        *(uint32_t*)(Ol + headoff + (size_t)r0 * Dm + cc) = lp;
        hp = pk_f16x2(v10, v11);
        upk_f16x2(hp, h0, h1);
        lp = pk_f16x2(v10 - h0, v11 - h1);
        *(uint32_t*)(Oh + headoff + (size_t)(r0 + 8) * Dm + cc) = hp;
        *(uint32_t*)(Ol + headoff + (size_t)(r0 + 8) * Dm + cc) = lp;
    }
}

// ---------------------------------------------------------------------------
extern "C" void kernel_launch(void* const* d_in, const int* in_sizes, int n_in,
                              void* d_out, int out_size)
{
    const float* x  = (const float*)d_in[0];
    const float* wq = (const float*)d_in[1];
    const float* bq = (const float*)d_in[2];
    const float* wk = (const float*)d_in[3];
    const float* bk = (const float*)d_in[4];
    const float* wv = (const float*)d_in[5];
    const float* bv = (const float*)d_in[6];
    const float* wo = (const float*)d_in[7];
    const float* bo = (const float*)d_in[8];
    float* out = (float*)d_out;

    fp16 *ahi, *alo, *wthi;
    fp16 *qh, *kh, *kl, *vh, *oh, *ol;
    cudaGetSymbolAddress((void**)&ahi,  g_Ahi);
    cudaGetSymbolAddress((void**)&alo,  g_Alo);
    cudaGetSymbolAddress((void**)&wthi, g_Wthi);
    cudaGetSymbolAddress((void**)&qh,   g_Qh);
    cudaGetSymbolAddress((void**)&kh,   g_Kh);
    cudaGetSymbolAddress((void**)&kl,   g_Kl);
    cudaGetSymbolAddress((void**)&vh,   g_Vh);
    cudaGetSymbolAddress((void**)&oh,   g_Oh);
    cudaGetSymbolAddress((void**)&ol,   g_Ol);

    cudaFuncSetAttribute(gemm_hmma,
                         cudaFuncAttributeMaxDynamicSharedMemorySize, HSMEM);
    cudaFuncSetAttribute(attn_hmma,
                         cudaFuncAttributeMaxDynamicSharedMemorySize, ATT_SMEM);

    const int n4 = MROWS * Dm / 4;
    dim3 gt(Dm / 32, Dm / 32);
    dim3 gg(Dm / 128, MROWS / 128);   // (8, 64)

    fsplit<<<(n4 + 255) / 256, 256>>>((const float4*)x, (uint2*)ahi, (uint2*)alo, n4);

    // Q: plain fp16 out (attention uses Qh only)
    wt_split<<<gt, 256>>>(wq, wthi);
    gemm_hmma<<<gg, 256, HSMEM>>>(ahi, alo, wthi, bq, nullptr, qh, nullptr, 2);
    // K: hi/lo out (attention QK 2nd term uses Kl)
    wt_split<<<gt, 256>>>(wk, wthi);
    gemm_hmma<<<gg, 256, HSMEM>>>(ahi, alo, wthi, bk, nullptr, kh, kl, 1);
    // V: plain fp16 out
    wt_split<<<gt, 256>>>(wv, wthi);
    gemm_hmma<<<gg, 256, HSMEM>>>(ahi, alo, wthi, bv, nullptr, vh, nullptr, 2);

    dim3 ga(Sq / 128, Bsz * Hn);      // (16, 64)
    attn_hmma<<<ga, 256, ATT_SMEM>>>(qh, kh, kl, vh, oh, ol);

    // O-projection: (Oh + Ol) @ Wo_hi, f32 out
    wt_split<<<gt, 256>>>(wo, wthi);
    gemm_hmma<<<gg, 256, HSMEM>>>(oh, ol, wthi, bo, out, nullptr, nullptr, 0);
}

// round 9
// speedup vs baseline: 1.6741x; 1.1298x over previous
#include <cuda_runtime.h>
#include <cuda_fp16.h>
#include <math.h>
#include <float.h>
#include <stdint.h>

// Problem constants
#define Bsz 4
#define Sq  2048
#define Dm  1024
#define Hn  16
#define HD  64
#define MROWS (Bsz * Sq)          // 8192

typedef __half fp16;

// ============================ PTX helpers ==================================
__device__ __forceinline__ uint32_t smem_u32(const void* p) {
    uint32_t a;
    asm("{ .reg .u64 t; cvta.to.shared.u64 t, %1; cvt.u32.u64 %0, t; }"
        : "=r"(a) : "l"(p));
    return a;
}
#define SWZ128(o) ((o) ^ (((o) >> 3) & 0x70))

__device__ __forceinline__ void cpa16(uint32_t saddr, const void* g) {
    asm volatile("cp.async.cg.shared.global [%0], [%1], 16;"
                 :: "r"(saddr), "l"(g) : "memory");
}
#define CP_COMMIT() asm volatile("cp.async.commit_group;" ::: "memory")
#define CP_WAIT1()  asm volatile("cp.async.wait_group 1;" ::: "memory")
#define CP_WAIT0()  asm volatile("cp.async.wait_group 0;" ::: "memory")

__device__ __forceinline__ void ldsm4(uint32_t* r, uint32_t addr) {
    asm volatile("ldmatrix.sync.aligned.m8n8.x4.shared.b16 {%0,%1,%2,%3}, [%4];"
                 : "=r"(r[0]), "=r"(r[1]), "=r"(r[2]), "=r"(r[3]) : "r"(addr));
}
__device__ __forceinline__ void ldsm4t(uint32_t* r, uint32_t addr) {
    asm volatile("ldmatrix.sync.aligned.m8n8.x4.trans.shared.b16 {%0,%1,%2,%3}, [%4];"
                 : "=r"(r[0]), "=r"(r[1]), "=r"(r[2]), "=r"(r[3]) : "r"(addr));
}
__device__ __forceinline__ void mma_f16(float* d, const uint32_t* a, const uint32_t* b) {
    asm volatile(
        "mma.sync.aligned.m16n8k16.row.col.f32.f16.f16.f32 "
        "{%0,%1,%2,%3}, {%4,%5,%6,%7}, {%8,%9}, {%0,%1,%2,%3};"
        : "+f"(d[0]), "+f"(d[1]), "+f"(d[2]), "+f"(d[3])
        : "r"(a[0]), "r"(a[1]), "r"(a[2]), "r"(a[3]), "r"(b[0]), "r"(b[1]));
}
__device__ __forceinline__ uint32_t pk_f16x2(float lo, float hi) {
    __half2 t = __floats2half2_rn(lo, hi);
    return *reinterpret_cast<uint32_t*>(&t);
}
__device__ __forceinline__ void upk_f16x2(uint32_t v, float& lo, float& hi) {
    __half2 t = *reinterpret_cast<__half2*>(&v);
    float2 f = __half22float2(t);
    lo = f.x; hi = f.y;
}

// ============================ scratch ======================================
__device__ fp16 g_Ahi[MROWS * Dm];
__device__ fp16 g_Alo[MROWS * Dm];
__device__ fp16 g_Wq[Dm * Dm];
__device__ fp16 g_Wk[Dm * Dm];
__device__ fp16 g_Wv[Dm * Dm];
__device__ fp16 g_Wo[Dm * Dm];
__device__ fp16 g_Qh[MROWS * Dm];
__device__ fp16 g_Kh[MROWS * Dm];
__device__ fp16 g_Kl[MROWS * Dm];
__device__ fp16 g_Vh[MROWS * Dm];
__device__ fp16 g_Oh[MROWS * Dm];
__device__ fp16 g_Ol[MROWS * Dm];

// =================== split conversion: f32 -> fp16 hi/lo ===================
__device__ __forceinline__ void hsplit(float x, fp16 &h, fp16 &l) {
    h = __float2half_rn(x);
    l = __float2half_rn(x - __half2float(h));
}

__global__ __launch_bounds__(256)
void fsplit(const float4* __restrict__ in, uint2* __restrict__ hi,
            uint2* __restrict__ lo, int n4)
{
    int i = blockIdx.x * 256 + threadIdx.x;
    if (i >= n4) return;
    float4 v = in[i];
    fp16 h0, h1, h2, h3, l0, l1, l2, l3;
    hsplit(v.x, h0, l0); hsplit(v.y, h1, l1);
    hsplit(v.z, h2, l2); hsplit(v.w, h3, l3);
    __half2 ph0 = __halves2half2(h0, h1), ph1 = __halves2half2(h2, h3);
    __half2 pl0 = __halves2half2(l0, l1), pl1 = __halves2half2(l2, l3);
    uint2 H, L;
    H.x = *(unsigned*)&ph0; H.y = *(unsigned*)&ph1;
    L.x = *(unsigned*)&pl0; L.y = *(unsigned*)&pl1;
    hi[i] = H; lo[i] = L;
}

// ====== all-four-weight transpose: W[K,N] f32 -> Wt[N,K] fp16 ==============
__global__ __launch_bounds__(256)
void wt4_split(const float* __restrict__ W0, const float* __restrict__ W1,
               const float* __restrict__ W2, const float* __restrict__ W3,
               fp16* __restrict__ T0, fp16* __restrict__ T1,
               fp16* __restrict__ T2, fp16* __restrict__ T3)
{
    const float* W = (blockIdx.z == 0) ? W0 : (blockIdx.z == 1) ? W1
                     : (blockIdx.z == 2) ? W2 : W3;
    fp16* T = (blockIdx.z == 0) ? T0 : (blockIdx.z == 1) ? T1
              : (blockIdx.z == 2) ? T2 : T3;
    __shared__ float t[32][33];
    int n0 = blockIdx.x * 32, k0 = blockIdx.y * 32;
    int tx = threadIdx.x & 31, ty = threadIdx.x >> 5;
    #pragma unroll
    for (int i = 0; i < 4; i++)
        t[ty + 8 * i][tx] = W[(size_t)(k0 + ty + 8 * i) * Dm + n0 + tx];
    __syncthreads();
    #pragma unroll
    for (int i = 0; i < 4; i++) {
        float v = t[tx][ty + 8 * i];
        T[(size_t)(n0 + ty + 8 * i) * Dm + k0 + tx] = __float2half_rn(v);
    }
}

// ================== HMMA fp16 2-term GEMM + bias ==========================
// 512 threads, tile 128x256, 16 warps (4m x 4n), warp tile 32x64.
// C = (Ah + Al) @ Bh^T + bias.
// mode 0: f32 -> Cf.  mode 1: fp16 hi/lo -> Ch/Cl.  mode 2: fp16 -> Ch.
#define HBK 64
#define HBUF 65536                 // Ah 16K | Al 16K | Bh 32K
#define HSMEM (2 * HBUF)           // 128KB
#define HCHUNKS (Dm / HBK)

__global__ __launch_bounds__(512, 1)
void gemm_hmma(const fp16* __restrict__ Ahi, const fp16* __restrict__ Alo,
               const fp16* __restrict__ Bhi,
               const float* __restrict__ bias,
               float* __restrict__ Cf, fp16* __restrict__ Ch,
               fp16* __restrict__ Cl, int mode)
{
    extern __shared__ __align__(1024) char smem[];
    const uint32_t sb = smem_u32(smem);

    const int tid  = threadIdx.x;
    const int wid  = tid >> 5;
    const int lane = tid & 31;
    const int wm   = wid & 3;          // 0..3
    const int wn   = wid >> 2;         // 0..3
    const int bm   = blockIdx.y * 128;
    const int bn   = blockIdx.x * 256;

    const int lrow = tid >> 3;         // 0..63
    const int lseg = tid & 7;

    float acc[2][8][4];
    #pragma unroll
    for (int fm = 0; fm < 2; fm++)
        #pragma unroll
        for (int fn = 0; fn < 8; fn++)
            #pragma unroll
            for (int e = 0; e < 4; e++) acc[fm][fn][e] = 0.0f;

    auto issue = [&](int c) {
        const uint32_t s0 = sb + (uint32_t)(c & 1) * HBUF;
        const size_t gofs = (size_t)c * HBK + lseg * 8;
        #pragma unroll
        for (int i = 0; i < 2; i++) {
            int row = lrow + i * 64;
            uint32_t so = SWZ128((uint32_t)(row * 128 + lseg * 16));
            cpa16(s0 + so,         Ahi + (size_t)(bm + row) * Dm + gofs);
            cpa16(s0 + 16384 + so, Alo + (size_t)(bm + row) * Dm + gofs);
        }
        #pragma unroll
        for (int i = 0; i < 4; i++) {
            int row = lrow + i * 64;
            uint32_t so = SWZ128((uint32_t)(row * 128 + lseg * 16));
            cpa16(s0 + 32768 + so, Bhi + (size_t)(bn + row) * Dm + gofs);
        }
    };

    const int a_row = wm * 32 + (lane & 15);
    const int a_sel = lane >> 4;
    const int b_row = wn * 64 + ((lane >> 4) << 3) + (lane & 7);
    const int b_sel = (lane >> 3) & 1;

    issue(0);
    CP_COMMIT();

    for (int c = 0; c < HCHUNKS; c++) {
        if (c + 1 < HCHUNKS) { issue(c + 1); CP_COMMIT(); CP_WAIT1(); }
        else { CP_COMMIT(); CP_WAIT0(); }
        __syncthreads();

        const uint32_t s0 = sb + (uint32_t)(c & 1) * HBUF;
        #pragma unroll
        for (int ks = 0; ks < 4; ks++) {
            uint32_t ah[2][4], al[2][4];
            #pragma unroll
            for (int fm = 0; fm < 2; fm++) {
                int row = a_row + fm * 16;
                int seg = 2 * ks + a_sel;
                uint32_t ad = s0 + SWZ128((uint32_t)(row * 128 + seg * 16));
                ldsm4(ah[fm], ad);
                ldsm4(al[fm], ad + 16384);
            }
            uint32_t bh[8][2];
            #pragma unroll
            for (int f2 = 0; f2 < 4; f2++) {
                int row = b_row + f2 * 16;
                int seg = 2 * ks + b_sel;
                uint32_t bd = s0 + 32768 + SWZ128((uint32_t)(row * 128 + seg * 16));
                uint32_t t[4];
                ldsm4(t, bd);
                bh[2*f2][0] = t[0]; bh[2*f2][1] = t[1];
                bh[2*f2+1][0] = t[2]; bh[2*f2+1][1] = t[3];
            }
            #pragma unroll
            for (int fm = 0; fm < 2; fm++)
                #pragma unroll
                for (int fn = 0; fn < 8; fn++) {
                    mma_f16(acc[fm][fn], ah[fm], bh[fn]);
                    mma_f16(acc[fm][fn], al[fm], bh[fn]);
                }
        }
        __syncthreads();
    }

    const int g  = lane >> 2;
    const int tq = lane & 3;
    #pragma unroll
    for (int fm = 0; fm < 2; fm++) {
        #pragma unroll
        for (int fn = 0; fn < 8; fn++) {
            int r0 = bm + wm * 32 + fm * 16 + g;
            int cc = bn + wn * 64 + fn * 8 + tq * 2;
            float b0 = bias[cc], b1 = bias[cc + 1];
            float v00 = acc[fm][fn][0] + b0, v01 = acc[fm][fn][1] + b1;
            float v10 = acc[fm][fn][2] + b0, v11 = acc[fm][fn][3] + b1;
            if (mode == 0) {
                *(float2*)(Cf + (size_t)r0 * Dm + cc) = make_float2(v00, v01);
                *(float2*)(Cf + (size_t)(r0 + 8) * Dm + cc) = make_float2(v10, v11);
            } else if (mode == 2) {
                *(uint32_t*)(Ch + (size_t)r0 * Dm + cc) = pk_f16x2(v00, v01);
                *(uint32_t*)(Ch + (size_t)(r0 + 8) * Dm + cc) = pk_f16x2(v10, v11);
            } else {
                uint32_t hp, lp; float hf0, hf1;
                hp = pk_f16x2(v00, v01);
                upk_f16x2(hp, hf0, hf1);
                lp = pk_f16x2(v00 - hf0, v01 - hf1);
                *(uint32_t*)(Ch + (size_t)r0 * Dm + cc) = hp;
                *(uint32_t*)(Cl + (size_t)r0 * Dm + cc) = lp;
                hp = pk_f16x2(v10, v11);
                upk_f16x2(hp, hf0, hf1);
                lp = pk_f16x2(v10 - hf0, v11 - hf1);
                *(uint32_t*)(Ch + (size_t)(r0 + 8) * Dm + cc) = hp;
                *(uint32_t*)(Cl + (size_t)(r0 + 8) * Dm + cc) = lp;
            }
        }
    }
}

// ---------------------------------------------------------------------------
// HMMA fp16 flash attention.  QK^T: 2-term  S = Qh*(Kh+Kl).  PV: 1 term.
// Br=128 (8 warps x m16), Bc=64, 2 CTAs/SM.
// smem: Q 16KB + 2 x (Kh|Kl|V = 24KB) = 64KB.
// ---------------------------------------------------------------------------
#define AQ_OFF  0
#define AKV_OFF 16384
#define AKVBUF  24576
#define ATT_SMEM (AKV_OFF + 2 * AKVBUF)   // 65536
#define C2EXP 0.18033688011112042f        // 0.125 * log2(e)

__global__ __launch_bounds__(256, 2)
void attn_hmma(const fp16* __restrict__ Qh,
               const fp16* __restrict__ Kh, const fp16* __restrict__ Kl,
               const fp16* __restrict__ Vh,
               fp16* __restrict__ Oh, fp16* __restrict__ Ol)
{
    extern __shared__ __align__(1024) char smem[];
    const uint32_t sb = smem_u32(smem);

    const int tid  = threadIdx.x;
    const int wid  = tid >> 5;
    const int lane = tid & 31;
    const int g    = lane >> 2;
    const int tq   = lane & 3;

    const int bh = blockIdx.y;
    const int b  = bh >> 4;
    const int h  = bh & 15;
    const int q0 = blockIdx.x * 128;
    const size_t headoff = (size_t)(b * Sq) * Dm + h * HD;

    const int lrq = tid >> 1;          // 0..127
    const int shq = (tid & 1) * 4;
    const int lrk = tid >> 2;          // 0..63
    const int sqk = (tid & 3) * 2;

    auto issueQ = [&]() {
        size_t gro = headoff + (size_t)(q0 + lrq) * Dm;
        #pragma unroll
        for (int u = 0; u < 4; u++) {
            int seg = shq + u;
            uint32_t so = SWZ128((uint32_t)(lrq * 128 + seg * 16));
            cpa16(sb + AQ_OFF + so, Qh + gro + seg * 8);
        }
    };
    auto issueKV = [&](int t) {
        const uint32_t s0 = sb + AKV_OFF + (uint32_t)(t & 1) * AKVBUF;
        size_t gro = headoff + (size_t)(t * 64 + lrk) * Dm;
        #pragma unroll
        for (int u = 0; u < 2; u++) {
            int seg = sqk + u;
            uint32_t so = SWZ128((uint32_t)(lrk * 128 + seg * 16));
            cpa16(s0 + so,         Kh + gro + seg * 8);
            cpa16(s0 + 8192 + so,  Kl + gro + seg * 8);
            cpa16(s0 + 16384 + so, Vh + gro + seg * 8);
        }
    };

    issueQ();  CP_COMMIT();
    issueKV(0); CP_COMMIT();
    CP_WAIT1();
    __syncthreads();

    uint32_t qh[4][4];
    {
        int arow = wid * 16 + (lane & 15);
        int asel = lane >> 4;
        #pragma unroll
        for (int ks = 0; ks < 4; ks++) {
            uint32_t ad = sb + AQ_OFF + SWZ128((uint32_t)(arow * 128 + (2 * ks + asel) * 16));
            ldsm4(qh[ks], ad);
        }
    }

    float o[8][4];
    #pragma unroll
    for (int fn = 0; fn < 8; fn++)
        #pragma unroll
        for (int e = 0; e < 4; e++) o[fn][e] = 0.0f;
    float m0 = -1e30f, m1 = -1e30f, l0 = 0.0f, l1 = 0.0f;

    const int kb_row = ((lane >> 4) << 3) + (lane & 7);
    const int kb_sel = (lane >> 3) & 1;
    const int vt_row = ((lane >> 3) & 1) * 8 + (lane & 7);
    const int vt_off = (lane >> 4) * 16;

    for (int t = 0; t < 32; t++) {
        __syncthreads();
        if (t + 1 < 32) { issueKV(t + 1); CP_COMMIT(); CP_WAIT1(); }
        else { CP_WAIT0(); }
        __syncthreads();

        const uint32_t s0 = sb + AKV_OFF + (uint32_t)(t & 1) * AKVBUF;

        // ---- S = Qh (Kh + Kl) : 2-term fp16, 64 keys ----
        float s[8][4];
        #pragma unroll
        for (int fn = 0; fn < 8; fn++)
            #pragma unroll
            for (int e = 0; e < 4; e++) s[fn][e] = 0.0f;

        #pragma unroll
        for (int ks = 0; ks < 4; ks++) {
            #pragma unroll
            for (int np = 0; np < 2; np++) {
                uint32_t kh0[4], kl0[4], kh1[4], kl1[4];
                uint32_t bd0 = s0 + SWZ128((uint32_t)(((2*np) * 16 + kb_row) * 128 +
                                                      (2 * ks + kb_sel) * 16));
                uint32_t bd1 = s0 + SWZ128((uint32_t)(((2*np+1) * 16 + kb_row) * 128 +
                                                      (2 * ks + kb_sel) * 16));
                ldsm4(kh0, bd0);
                ldsm4(kl0, bd0 + 8192);
                ldsm4(kh1, bd1);
                ldsm4(kl1, bd1 + 8192);
                float* sp = (float*)s[4*np];
                mma_f16(sp + 0,  qh[ks], kh0);
                mma_f16(sp + 4,  qh[ks], kh0 + 2);
                mma_f16(sp + 8,  qh[ks], kh1);
                mma_f16(sp + 12, qh[ks], kh1 + 2);
                mma_f16(sp + 0,  qh[ks], kl0);
                mma_f16(sp + 4,  qh[ks], kl0 + 2);
                mma_f16(sp + 8,  qh[ks], kl1);
                mma_f16(sp + 12, qh[ks], kl1 + 2);
            }
        }

        // ---- online softmax ----
        float mx0 = -1e30f, mx1 = -1e30f;
        #pragma unroll
        for (int fn = 0; fn < 8; fn++) {
            mx0 = fmaxf(mx0, fmaxf(s[fn][0], s[fn][1]));
            mx1 = fmaxf(mx1, fmaxf(s[fn][2], s[fn][3]));
        }
        mx0 = fmaxf(mx0, __shfl_xor_sync(0xffffffffu, mx0, 1));
        mx0 = fmaxf(mx0, __shfl_xor_sync(0xffffffffu, mx0, 2));
        mx1 = fmaxf(mx1, __shfl_xor_sync(0xffffffffu, mx1, 1));
        mx1 = fmaxf(mx1, __shfl_xor_sync(0xffffffffu, mx1, 2));
        float nm0 = fmaxf(m0, mx0);
        float nm1 = fmaxf(m1, mx1);

        float sum0 = 0.0f, sum1 = 0.0f;
        #pragma unroll
        for (int fn = 0; fn < 8; fn++) {
            s[fn][0] = exp2f((s[fn][0] - nm0) * C2EXP);
            s[fn][1] = exp2f((s[fn][1] - nm0) * C2EXP);
            s[fn][2] = exp2f((s[fn][2] - nm1) * C2EXP);
            s[fn][3] = exp2f((s[fn][3] - nm1) * C2EXP);
            sum0 += s[fn][0] + s[fn][1];
            sum1 += s[fn][2] + s[fn][3];
        }
        sum0 += __shfl_xor_sync(0xffffffffu, sum0, 1);
        sum0 += __shfl_xor_sync(0xffffffffu, sum0, 2);
        sum1 += __shfl_xor_sync(0xffffffffu, sum1, 1);
        sum1 += __shfl_xor_sync(0xffffffffu, sum1, 2);

        float c0 = exp2f((m0 - nm0) * C2EXP);
        float c1 = exp2f((m1 - nm1) * C2EXP);
        l0 = l0 * c0 + sum0;  m0 = nm0;
        l1 = l1 * c1 + sum1;  m1 = nm1;
        #pragma unroll
        for (int fn = 0; fn < 8; fn++) {
            o[fn][0] *= c0; o[fn][1] *= c0;
            o[fn][2] *= c1; o[fn][3] *= c1;
        }

        // ---- O += P V : plain fp16 P, single V, 64 keys ----
        #pragma unroll
        for (int kc = 0; kc < 4; kc++) {
            uint32_t ap[4];
            #pragma unroll
            for (int q = 0; q < 4; q++) {
                const float* sv = s[2 * kc + (q >> 1)];
                ap[q] = pk_f16x2(sv[(q & 1) * 2], sv[(q & 1) * 2 + 1]);
            }
            #pragma unroll
            for (int dp = 0; dp < 2; dp++) {
                int d0 = dp * 32;
                uint32_t vd0 = s0 + 16384 +
                    SWZ128((uint32_t)((kc * 16 + vt_row) * 128 + d0 * 2 + vt_off));
                uint32_t vd1 = s0 + 16384 +
                    SWZ128((uint32_t)((kc * 16 + vt_row) * 128 + (d0 + 16) * 2 + vt_off));
                uint32_t vh0[4], vh1[4];
                ldsm4t(vh0, vd0);
                ldsm4t(vh1, vd1);
                float* op = (float*)o[4 * dp];
                mma_f16(op + 0,  ap, vh0);
                mma_f16(op + 4,  ap, vh0 + 2);
                mma_f16(op + 8,  ap, vh1);
                mma_f16(op + 12, ap, vh1 + 2);
            }
        }
    }

    // ---- normalize + store fp16 hi/lo ----
    float inv0 = 1.0f / l0, inv1 = 1.0f / l1;
    int r0 = q0 + wid * 16 + g;
    #pragma unroll
    for (int fn = 0; fn < 8; fn++) {
        int cc = fn * 8 + tq * 2;
        float v00 = o[fn][0] * inv0, v01 = o[fn][1] * inv0;
        float v10 = o[fn][2] * inv1, v11 = o[fn][3] * inv1;
        uint32_t hp, lp; float h0, h1;
        hp = pk_f16x2(v00, v01);
        upk_f16x2(hp, h0, h1);
        lp = pk_f16x2(v00 - h0, v01 - h1);
        *(uint32_t*)(Oh + headoff + (size_t)r0 * Dm + cc) = hp;
        *(uint32_t*)(Ol + headoff + (size_t)r0 * Dm + cc) = lp;
        hp = pk_f16x2(v10, v11);
        upk_f16x2(hp, h0, h1);
        lp = pk_f16x2(v10 - h0, v11 - h1);
        *(uint32_t*)(Oh + headoff + (size_t)(r0 + 8) * Dm + cc) = hp;
        *(uint32_t*)(Ol + headoff + (size_t)(r0 + 8) * Dm + cc) = lp;
    }
}

// ---------------------------------------------------------------------------
extern "C" void kernel_launch(void* const* d_in, const int* in_sizes, int n_in,
                              void* d_out, int out_size)
{
    const float* x  = (const float*)d_in[0];
    const float* wq = (const float*)d_in[1];
    const float* bq = (const float*)d_in[2];
    const float* wk = (const float*)d_in[3];
    const float* bk = (const float*)d_in[4];
    const float* wv = (const float*)d_in[5];
    const float* bv = (const float*)d_in[6];
    const float* wo = (const float*)d_in[7];
    const float* bo = (const float*)d_in[8];
    float* out = (float*)d_out;

    fp16 *ahi, *alo, *wtq, *wtk, *wtv, *wto;
    fp16 *qh, *kh, *kl, *vh, *oh, *ol;
    cudaGetSymbolAddress((void**)&ahi, g_Ahi);
    cudaGetSymbolAddress((void**)&alo, g_Alo);
    cudaGetSymbolAddress((void**)&wtq, g_Wq);
    cudaGetSymbolAddress((void**)&wtk, g_Wk);
    cudaGetSymbolAddress((void**)&wtv, g_Wv);
    cudaGetSymbolAddress((void**)&wto, g_Wo);
    cudaGetSymbolAddress((void**)&qh,  g_Qh);
    cudaGetSymbolAddress((void**)&kh,  g_Kh);
    cudaGetSymbolAddress((void**)&kl,  g_Kl);
    cudaGetSymbolAddress((void**)&vh,  g_Vh);
    cudaGetSymbolAddress((void**)&oh,  g_Oh);
    cudaGetSymbolAddress((void**)&ol,  g_Ol);

    cudaFuncSetAttribute(gemm_hmma,
                         cudaFuncAttributeMaxDynamicSharedMemorySize, HSMEM);
    cudaFuncSetAttribute(attn_hmma,
                         cudaFuncAttributeMaxDynamicSharedMemorySize, ATT_SMEM);

    const int n4 = MROWS * Dm / 4;
    dim3 gt(Dm / 32, Dm / 32, 4);
    dim3 gg(Dm / 256, MROWS / 128);   // (4, 64)

    fsplit<<<(n4 + 255) / 256, 256>>>((const float4*)x, (uint2*)ahi, (uint2*)alo, n4);
    wt4_split<<<gt, 256>>>(wq, wk, wv, wo, wtq, wtk, wtv, wto);

    gemm_hmma<<<gg, 512, HSMEM>>>(ahi, alo, wtq, bq, nullptr, qh, nullptr, 2);
    gemm_hmma<<<gg, 512, HSMEM>>>(ahi, alo, wtk, bk, nullptr, kh, kl, 1);
    gemm_hmma<<<gg, 512, HSMEM>>>(ahi, alo, wtv, bv, nullptr, vh, nullptr, 2);

    dim3 ga(Sq / 128, Bsz * Hn);      // (16, 64)
    attn_hmma<<<ga, 256, ATT_SMEM>>>(qh, kh, kl, vh, oh, ol);

    gemm_hmma<<<gg, 512, HSMEM>>>(oh, ol, wto, bo, out, nullptr, nullptr, 0);
}

// round 10
// speedup vs baseline: 1.7025x; 1.0169x over previous
#include <cuda_runtime.h>
#include <cuda_fp16.h>
#include <math.h>
#include <float.h>
#include <stdint.h>

// Problem constants
#define Bsz 4
#define Sq  2048
#define Dm  1024
#define Hn  16
#define HD  64
#define MROWS (Bsz * Sq)          // 8192

typedef __half fp16;

// ============================ PTX helpers ==================================
__device__ __forceinline__ uint32_t smem_u32(const void* p) {
    uint32_t a;
    asm("{ .reg .u64 t; cvta.to.shared.u64 t, %1; cvt.u32.u64 %0, t; }"
        : "=r"(a) : "l"(p));
    return a;
}
#define SWZ128(o) ((o) ^ (((o) >> 3) & 0x70))

__device__ __forceinline__ void cpa16(uint32_t saddr, const void* g) {
    asm volatile("cp.async.cg.shared.global [%0], [%1], 16;"
                 :: "r"(saddr), "l"(g) : "memory");
}
#define CP_COMMIT() asm volatile("cp.async.commit_group;" ::: "memory")
#define CP_WAIT2()  asm volatile("cp.async.wait_group 2;" ::: "memory")
#define CP_WAIT1()  asm volatile("cp.async.wait_group 1;" ::: "memory")
#define CP_WAIT0()  asm volatile("cp.async.wait_group 0;" ::: "memory")

__device__ __forceinline__ void ldsm4(uint32_t* r, uint32_t addr) {
    asm volatile("ldmatrix.sync.aligned.m8n8.x4.shared.b16 {%0,%1,%2,%3}, [%4];"
                 : "=r"(r[0]), "=r"(r[1]), "=r"(r[2]), "=r"(r[3]) : "r"(addr));
}
__device__ __forceinline__ void ldsm4t(uint32_t* r, uint32_t addr) {
    asm volatile("ldmatrix.sync.aligned.m8n8.x4.trans.shared.b16 {%0,%1,%2,%3}, [%4];"
                 : "=r"(r[0]), "=r"(r[1]), "=r"(r[2]), "=r"(r[3]) : "r"(addr));
}
__device__ __forceinline__ void mma_f16(float* d, const uint32_t* a, const uint32_t* b) {
    asm volatile(
        "mma.sync.aligned.m16n8k16.row.col.f32.f16.f16.f32 "
        "{%0,%1,%2,%3}, {%4,%5,%6,%7}, {%8,%9}, {%0,%1,%2,%3};"
        : "+f"(d[0]), "+f"(d[1]), "+f"(d[2]), "+f"(d[3])
        : "r"(a[0]), "r"(a[1]), "r"(a[2]), "r"(a[3]), "r"(b[0]), "r"(b[1]));
}
__device__ __forceinline__ uint32_t pk_f16x2(float lo, float hi) {
    __half2 t = __floats2half2_rn(lo, hi);
    return *reinterpret_cast<uint32_t*>(&t);
}
__device__ __forceinline__ void upk_f16x2(uint32_t v, float& lo, float& hi) {
    __half2 t = *reinterpret_cast<__half2*>(&v);
    float2 f = __half22float2(t);
    lo = f.x; hi = f.y;
}

// ============================ scratch ======================================
__device__ fp16 g_Ahi[MROWS * Dm];
__device__ fp16 g_Alo[MROWS * Dm];
__device__ fp16 g_Wq[Dm * Dm];
__device__ fp16 g_Wk[Dm * Dm];
__device__ fp16 g_Wv[Dm * Dm];
__device__ fp16 g_Wo[Dm * Dm];
__device__ fp16 g_Qh[MROWS * Dm];
__device__ fp16 g_Kh[MROWS * Dm];
__device__ fp16 g_Kl[MROWS * Dm];
__device__ fp16 g_Vh[MROWS * Dm];
__device__ fp16 g_Oh[MROWS * Dm];
__device__ fp16 g_Ol[MROWS * Dm];

// =================== split conversion: f32 -> fp16 hi/lo ===================
__device__ __forceinline__ void hsplit(float x, fp16 &h, fp16 &l) {
    h = __float2half_rn(x);
    l = __float2half_rn(x - __half2float(h));
}

__global__ __launch_bounds__(256)
void fsplit(const float4* __restrict__ in, uint2* __restrict__ hi,
            uint2* __restrict__ lo, int n4)
{
    int i = blockIdx.x * 256 + threadIdx.x;
    if (i >= n4) return;
    float4 v = in[i];
    fp16 h0, h1, h2, h3, l0, l1, l2, l3;
    hsplit(v.x, h0, l0); hsplit(v.y, h1, l1);
    hsplit(v.z, h2, l2); hsplit(v.w, h3, l3);
    __half2 ph0 = __halves2half2(h0, h1), ph1 = __halves2half2(h2, h3);
    __half2 pl0 = __halves2half2(l0, l1), pl1 = __halves2half2(l2, l3);
    uint2 H, L;
    H.x = *(unsigned*)&ph0; H.y = *(unsigned*)&ph1;
    L.x = *(unsigned*)&pl0; L.y = *(unsigned*)&pl1;
    hi[i] = H; lo[i] = L;
}

// ====== all-four-weight transpose: W[K,N] f32 -> Wt[N,K] fp16 ==============
__global__ __launch_bounds__(256)
void wt4_split(const float* __restrict__ W0, const float* __restrict__ W1,
               const float* __restrict__ W2, const float* __restrict__ W3,
               fp16* __restrict__ T0, fp16* __restrict__ T1,
               fp16* __restrict__ T2, fp16* __restrict__ T3)
{
    const float* W = (blockIdx.z == 0) ? W0 : (blockIdx.z == 1) ? W1
                     : (blockIdx.z == 2) ? W2 : W3;
    fp16* T = (blockIdx.z == 0) ? T0 : (blockIdx.z == 1) ? T1
              : (blockIdx.z == 2) ? T2 : T3;
    __shared__ float t[32][33];
    int n0 = blockIdx.x * 32, k0 = blockIdx.y * 32;
    int tx = threadIdx.x & 31, ty = threadIdx.x >> 5;
    #pragma unroll
    for (int i = 0; i < 4; i++)
        t[ty + 8 * i][tx] = W[(size_t)(k0 + ty + 8 * i) * Dm + n0 + tx];
    __syncthreads();
    #pragma unroll
    for (int i = 0; i < 4; i++) {
        float v = t[tx][ty + 8 * i];
        T[(size_t)(n0 + ty + 8 * i) * Dm + k0 + tx] = __float2half_rn(v);
    }
}

// ================== HMMA fp16 2-term GEMM core ============================
// 512 threads, tile 128x256, warp tile 32x64, 3-stage cp.async pipeline,
// ONE __syncthreads per K-chunk.
// C = (Ah + Al) @ Bh^T + bias.
// mode 0: f32 -> Cf.  mode 1: fp16 hi/lo -> Ch/Cl.  mode 2: fp16 -> Ch.
#define HBK 64
#define HSTAGE 65536               // Ah 16K | Al 16K | Bh 32K
#define HSMEM (3 * HSTAGE)         // 192KB
#define HCHUNKS (Dm / HBK)

__device__ __forceinline__
void gemm_core(const fp16* __restrict__ Ahi, const fp16* __restrict__ Alo,
               const fp16* __restrict__ Bhi, const float* __restrict__ bias,
               float* __restrict__ Cf, fp16* __restrict__ Ch,
               fp16* __restrict__ Cl, int mode, char* smem)
{
    const uint32_t sb = smem_u32(smem);
    const int tid  = threadIdx.x;
    const int wid  = tid >> 5;
    const int lane = tid & 31;
    const int wm   = wid & 3;
    const int wn   = wid >> 2;
    const int bm   = blockIdx.y * 128;
    const int bn   = blockIdx.x * 256;

    const int lrow = tid >> 3;
    const int lseg = tid & 7;

    float acc[2][8][4];
    #pragma unroll
    for (int fm = 0; fm < 2; fm++)
        #pragma unroll
        for (int fn = 0; fn < 8; fn++)
            #pragma unroll
            for (int e = 0; e < 4; e++) acc[fm][fn][e] = 0.0f;

    auto issue = [&](int c) {
        const uint32_t s0 = sb + (uint32_t)(c % 3) * HSTAGE;
        const size_t gofs = (size_t)c * HBK + lseg * 8;
        #pragma unroll
        for (int i = 0; i < 2; i++) {
            int row = lrow + i * 64;
            uint32_t so = SWZ128((uint32_t)(row * 128 + lseg * 16));
            cpa16(s0 + so,         Ahi + (size_t)(bm + row) * Dm + gofs);
            cpa16(s0 + 16384 + so, Alo + (size_t)(bm + row) * Dm + gofs);
        }
        #pragma unroll
        for (int i = 0; i < 4; i++) {
            int row = lrow + i * 64;
            uint32_t so = SWZ128((uint32_t)(row * 128 + lseg * 16));
            cpa16(s0 + 32768 + so, Bhi + (size_t)(bn + row) * Dm + gofs);
        }
    };

    const int a_row = wm * 32 + (lane & 15);
    const int a_sel = lane >> 4;
    const int b_row = wn * 64 + ((lane >> 4) << 3) + (lane & 7);
    const int b_sel = (lane >> 3) & 1;

    issue(0); CP_COMMIT();
    issue(1); CP_COMMIT();

    for (int c = 0; c < HCHUNKS; c++) {
        if (c + 1 < HCHUNKS) CP_WAIT1(); else CP_WAIT0();
        __syncthreads();
        if (c + 2 < HCHUNKS) { issue(c + 2); CP_COMMIT(); }

        const uint32_t s0 = sb + (uint32_t)(c % 3) * HSTAGE;
        #pragma unroll
        for (int ks = 0; ks < 4; ks++) {
            uint32_t ah[2][4], al[2][4];
            #pragma unroll
            for (int fm = 0; fm < 2; fm++) {
                int row = a_row + fm * 16;
                int seg = 2 * ks + a_sel;
                uint32_t ad = s0 + SWZ128((uint32_t)(row * 128 + seg * 16));
                ldsm4(ah[fm], ad);
                ldsm4(al[fm], ad + 16384);
            }
            uint32_t bh[8][2];
            #pragma unroll
            for (int f2 = 0; f2 < 4; f2++) {
                int row = b_row + f2 * 16;
                int seg = 2 * ks + b_sel;
                uint32_t bd = s0 + 32768 + SWZ128((uint32_t)(row * 128 + seg * 16));
                uint32_t t[4];
                ldsm4(t, bd);
                bh[2*f2][0] = t[0]; bh[2*f2][1] = t[1];
                bh[2*f2+1][0] = t[2]; bh[2*f2+1][1] = t[3];
            }
            #pragma unroll
            for (int fm = 0; fm < 2; fm++)
                #pragma unroll
                for (int fn = 0; fn < 8; fn++) {
                    mma_f16(acc[fm][fn], ah[fm], bh[fn]);
                    mma_f16(acc[fm][fn], al[fm], bh[fn]);
                }
        }
    }

    const int g  = lane >> 2;
    const int tq = lane & 3;
    #pragma unroll
    for (int fm = 0; fm < 2; fm++) {
        #pragma unroll
        for (int fn = 0; fn < 8; fn++) {
            int r0 = bm + wm * 32 + fm * 16 + g;
            int cc = bn + wn * 64 + fn * 8 + tq * 2;
            float b0 = bias[cc], b1 = bias[cc + 1];
            float v00 = acc[fm][fn][0] + b0, v01 = acc[fm][fn][1] + b1;
            float v10 = acc[fm][fn][2] + b0, v11 = acc[fm][fn][3] + b1;
            if (mode == 0) {
                *(float2*)(Cf + (size_t)r0 * Dm + cc) = make_float2(v00, v01);
                *(float2*)(Cf + (size_t)(r0 + 8) * Dm + cc) = make_float2(v10, v11);
            } else if (mode == 2) {
                *(uint32_t*)(Ch + (size_t)r0 * Dm + cc) = pk_f16x2(v00, v01);
                *(uint32_t*)(Ch + (size_t)(r0 + 8) * Dm + cc) = pk_f16x2(v10, v11);
            } else {
                uint32_t hp, lp; float hf0, hf1;
                hp = pk_f16x2(v00, v01);
                upk_f16x2(hp, hf0, hf1);
                lp = pk_f16x2(v00 - hf0, v01 - hf1);
                *(uint32_t*)(Ch + (size_t)r0 * Dm + cc) = hp;
                *(uint32_t*)(Cl + (size_t)r0 * Dm + cc) = lp;
                hp = pk_f16x2(v10, v11);
                upk_f16x2(hp, hf0, hf1);
                lp = pk_f16x2(v10 - hf0, v11 - hf1);
                *(uint32_t*)(Ch + (size_t)(r0 + 8) * Dm + cc) = hp;
                *(uint32_t*)(Cl + (size_t)(r0 + 8) * Dm + cc) = lp;
            }
        }
    }
}

// Fused Q/K/V projections: blockIdx.z selects weight/bias/output/mode.
__global__ __launch_bounds__(512, 1)
void gemm_qkv(const fp16* __restrict__ Ahi, const fp16* __restrict__ Alo,
              const fp16* __restrict__ Wq, const fp16* __restrict__ Wk,
              const fp16* __restrict__ Wv,
              const float* __restrict__ bq, const float* __restrict__ bk,
              const float* __restrict__ bv,
              fp16* __restrict__ Qh, fp16* __restrict__ Kh,
              fp16* __restrict__ Kl, fp16* __restrict__ Vh)
{
    extern __shared__ __align__(1024) char smem[];
    if (blockIdx.z == 0)
        gemm_core(Ahi, Alo, Wq, bq, nullptr, Qh, nullptr, 2, smem);
    else if (blockIdx.z == 1)
        gemm_core(Ahi, Alo, Wk, bk, nullptr, Kh, Kl, 1, smem);
    else
        gemm_core(Ahi, Alo, Wv, bv, nullptr, Vh, nullptr, 2, smem);
}

// O-projection: (Oh + Ol) @ Wo^T + bo -> f32 out.
__global__ __launch_bounds__(512, 1)
void gemm_o(const fp16* __restrict__ Ohi, const fp16* __restrict__ Olo,
            const fp16* __restrict__ Wo, const float* __restrict__ bo,
            float* __restrict__ out)
{
    extern __shared__ __align__(1024) char smem[];
    gemm_core(Ohi, Olo, Wo, bo, out, nullptr, nullptr, 0, smem);
}

// ---------------------------------------------------------------------------
// HMMA fp16 flash attention.  QK^T: 2-term  S = Qh*(Kh+Kl).  PV: 1 term.
// Br=128 (8 warps x m16), Bc=64, 2 CTAs/SM, 3-stage KV pipeline, 1 sync/tile.
// smem: Q 16KB + 3 x (Kh|Kl|V = 24KB) = 88KB.
// ---------------------------------------------------------------------------
#define AQ_OFF  0
#define AKV_OFF 16384
#define AKVBUF  24576
#define ATT_SMEM (AKV_OFF + 3 * AKVBUF)   // 90112
#define C2EXP 0.18033688011112042f        // 0.125 * log2(e)

__global__ __launch_bounds__(256, 2)
void attn_hmma(const fp16* __restrict__ Qh,
               const fp16* __restrict__ Kh, const fp16* __restrict__ Kl,
               const fp16* __restrict__ Vh,
               fp16* __restrict__ Oh, fp16* __restrict__ Ol)
{
    extern __shared__ __align__(1024) char smem[];
    const uint32_t sb = smem_u32(smem);

    const int tid  = threadIdx.x;
    const int wid  = tid >> 5;
    const int lane = tid & 31;
    const int g    = lane >> 2;
    const int tq   = lane & 3;

    const int bh = blockIdx.y;
    const int b  = bh >> 4;
    const int h  = bh & 15;
    const int q0 = blockIdx.x * 128;
    const size_t headoff = (size_t)(b * Sq) * Dm + h * HD;

    const int lrq = tid >> 1;          // 0..127
    const int shq = (tid & 1) * 4;
    const int lrk = tid >> 2;          // 0..63
    const int sqk = (tid & 3) * 2;

    auto issueQ = [&]() {
        size_t gro = headoff + (size_t)(q0 + lrq) * Dm;
        #pragma unroll
        for (int u = 0; u < 4; u++) {
            int seg = shq + u;
            uint32_t so = SWZ128((uint32_t)(lrq * 128 + seg * 16));
            cpa16(sb + AQ_OFF + so, Qh + gro + seg * 8);
        }
    };
    auto issueKV = [&](int t) {
        const uint32_t s0 = sb + AKV_OFF + (uint32_t)(t % 3) * AKVBUF;
        size_t gro = headoff + (size_t)(t * 64 + lrk) * Dm;
        #pragma unroll
        for (int u = 0; u < 2; u++) {
            int seg = sqk + u;
            uint32_t so = SWZ128((uint32_t)(lrk * 128 + seg * 16));
            cpa16(s0 + so,         Kh + gro + seg * 8);
            cpa16(s0 + 8192 + so,  Kl + gro + seg * 8);
            cpa16(s0 + 16384 + so, Vh + gro + seg * 8);
        }
    };

    issueQ();   CP_COMMIT();
    issueKV(0); CP_COMMIT();
    issueKV(1); CP_COMMIT();
    CP_WAIT2();          // Q group done
    __syncthreads();

    uint32_t qh[4][4];
    {
        int arow = wid * 16 + (lane & 15);
        int asel = lane >> 4;
        #pragma unroll
        for (int ks = 0; ks < 4; ks++) {
            uint32_t ad = sb + AQ_OFF + SWZ128((uint32_t)(arow * 128 + (2 * ks + asel) * 16));
            ldsm4(qh[ks], ad);
        }
    }

    float o[8][4];
    #pragma unroll
    for (int fn = 0; fn < 8; fn++)
        #pragma unroll
        for (int e = 0; e < 4; e++) o[fn][e] = 0.0f;
    float m0 = -1e30f, m1 = -1e30f, l0 = 0.0f, l1 = 0.0f;

    const int kb_row = ((lane >> 4) << 3) + (lane & 7);
    const int kb_sel = (lane >> 3) & 1;
    const int vt_row = ((lane >> 3) & 1) * 8 + (lane & 7);
    const int vt_off = (lane >> 4) * 16;

    for (int t = 0; t < 32; t++) {
        if (t + 1 < 32) CP_WAIT1(); else CP_WAIT0();
        __syncthreads();
        if (t + 2 < 32) { issueKV(t + 2); CP_COMMIT(); }

        const uint32_t s0 = sb + AKV_OFF + (uint32_t)(t % 3) * AKVBUF;

        // ---- S = Qh (Kh + Kl) : 2-term fp16, 64 keys ----
        float s[8][4];
        #pragma unroll
        for (int fn = 0; fn < 8; fn++)
            #pragma unroll
            for (int e = 0; e < 4; e++) s[fn][e] = 0.0f;

        #pragma unroll
        for (int ks = 0; ks < 4; ks++) {
            #pragma unroll
            for (int np = 0; np < 2; np++) {
                uint32_t kh0[4], kl0[4], kh1[4], kl1[4];
                uint32_t bd0 = s0 + SWZ128((uint32_t)(((2*np) * 16 + kb_row) * 128 +
                                                      (2 * ks + kb_sel) * 16));
                uint32_t bd1 = s0 + SWZ128((uint32_t)(((2*np+1) * 16 + kb_row) * 128 +
                                                      (2 * ks + kb_sel) * 16));
                ldsm4(kh0, bd0);
                ldsm4(kl0, bd0 + 8192);
                ldsm4(kh1, bd1);
                ldsm4(kl1, bd1 + 8192);
                float* sp = (float*)s[4*np];
                mma_f16(sp + 0,  qh[ks], kh0);
                mma_f16(sp + 4,  qh[ks], kh0 + 2);
                mma_f16(sp + 8,  qh[ks], kh1);
                mma_f16(sp + 12, qh[ks], kh1 + 2);
                mma_f16(sp + 0,  qh[ks], kl0);
                mma_f16(sp + 4,  qh[ks], kl0 + 2);
                mma_f16(sp + 8,  qh[ks], kl1);
                mma_f16(sp + 12, qh[ks], kl1 + 2);
            }
        }

        // ---- online softmax ----
        float mx0 = -1e30f, mx1 = -1e30f;
        #pragma unroll
        for (int fn = 0; fn < 8; fn++) {
            mx0 = fmaxf(mx0, fmaxf(s[fn][0], s[fn][1]));
            mx1 = fmaxf(mx1, fmaxf(s[fn][2], s[fn][3]));
        }
        mx0 = fmaxf(mx0, __shfl_xor_sync(0xffffffffu, mx0, 1));
        mx0 = fmaxf(mx0, __shfl_xor_sync(0xffffffffu, mx0, 2));
        mx1 = fmaxf(mx1, __shfl_xor_sync(0xffffffffu, mx1, 1));
        mx1 = fmaxf(mx1, __shfl_xor_sync(0xffffffffu, mx1, 2));
        float nm0 = fmaxf(m0, mx0);
        float nm1 = fmaxf(m1, mx1);

        float sum0 = 0.0f, sum1 = 0.0f;
        #pragma unroll
        for (int fn = 0; fn < 8; fn++) {
            s[fn][0] = exp2f((s[fn][0] - nm0) * C2EXP);
            s[fn][1] = exp2f((s[fn][1] - nm0) * C2EXP);
            s[fn][2] = exp2f((s[fn][2] - nm1) * C2EXP);
            s[fn][3] = exp2f((s[fn][3] - nm1) * C2EXP);
            sum0 += s[fn][0] + s[fn][1];
            sum1 += s[fn][2] + s[fn][3];
        }
        sum0 += __shfl_xor_sync(0xffffffffu, sum0, 1);
        sum0 += __shfl_xor_sync(0xffffffffu, sum0, 2);
        sum1 += __shfl_xor_sync(0xffffffffu, sum1, 1);
        sum1 += __shfl_xor_sync(0xffffffffu, sum1, 2);

        float c0 = exp2f((m0 - nm0) * C2EXP);
        float c1 = exp2f((m1 - nm1) * C2EXP);
        l0 = l0 * c0 + sum0;  m0 = nm0;
        l1 = l1 * c1 + sum1;  m1 = nm1;
        #pragma unroll
        for (int fn = 0; fn < 8; fn++) {
            o[fn][0] *= c0; o[fn][1] *= c0;
            o[fn][2] *= c1; o[fn][3] *= c1;
        }

        // ---- O += P V : plain fp16 P, single V, 64 keys ----
        #pragma unroll
        for (int kc = 0; kc < 4; kc++) {
            uint32_t ap[4];
            #pragma unroll
            for (int q = 0; q < 4; q++) {
                const float* sv = s[2 * kc + (q >> 1)];
                ap[q] = pk_f16x2(sv[(q & 1) * 2], sv[(q & 1) * 2 + 1]);
            }
            #pragma unroll
            for (int dp = 0; dp < 2; dp++) {
                int d0 = dp * 32;
                uint32_t vd0 = s0 + 16384 +
                    SWZ128((uint32_t)((kc * 16 + vt_row) * 128 + d0 * 2 + vt_off));
                uint32_t vd1 = s0 + 16384 +
                    SWZ128((uint32_t)((kc * 16 + vt_row) * 128 + (d0 + 16) * 2 + vt_off));
                uint32_t vh0[4], vh1[4];
                ldsm4t(vh0, vd0);
                ldsm4t(vh1, vd1);
                float* op = (float*)o[4 * dp];
                mma_f16(op + 0,  ap, vh0);
                mma_f16(op + 4,  ap, vh0 + 2);
                mma_f16(op + 8,  ap, vh1);
                mma_f16(op + 12, ap, vh1 + 2);
            }
        }
    }

    // ---- normalize + store fp16 hi/lo ----
    float inv0 = 1.0f / l0, inv1 = 1.0f / l1;
    int r0 = q0 + wid * 16 + g;
    #pragma unroll
    for (int fn = 0; fn < 8; fn++) {
        int cc = fn * 8 + tq * 2;
        float v00 = o[fn][0] * inv0, v01 = o[fn][1] * inv0;
        float v10 = o[fn][2] * inv1, v11 = o[fn][3] * inv1;
        uint32_t hp, lp; float h0, h1;
        hp = pk_f16x2(v00, v01);
        upk_f16x2(hp, h0, h1);
        lp = pk_f16x2(v00 - h0, v01 - h1);
        *(uint32_t*)(Oh + headoff + (size_t)r0 * Dm + cc) = hp;
        *(uint32_t*)(Ol + headoff + (size_t)r0 * Dm + cc) = lp;
        hp = pk_f16x2(v10, v11);
        upk_f16x2(hp, h0, h1);
        lp = pk_f16x2(v10 - h0, v11 - h1);
        *(uint32_t*)(Oh + headoff + (size_t)(r0 + 8) * Dm + cc) = hp;
        *(uint32_t*)(Ol + headoff + (size_t)(r0 + 8) * Dm + cc) = lp;
    }
}

// ---------------------------------------------------------------------------
extern "C" void kernel_launch(void* const* d_in, const int* in_sizes, int n_in,
                              void* d_out, int out_size)
{
    const float* x  = (const float*)d_in[0];
    const float* wq = (const float*)d_in[1];
    const float* bq = (const float*)d_in[2];
    const float* wk = (const float*)d_in[3];
    const float* bk = (const float*)d_in[4];
    const float* wv = (const float*)d_in[5];
    const float* bv = (const float*)d_in[6];
    const float* wo = (const float*)d_in[7];
    const float* bo = (const float*)d_in[8];
    float* out = (float*)d_out;

    fp16 *ahi, *alo, *wtq, *wtk, *wtv, *wto;
    fp16 *qh, *kh, *kl, *vh, *oh, *ol;
    cudaGetSymbolAddress((void**)&ahi, g_Ahi);
    cudaGetSymbolAddress((void**)&alo, g_Alo);
    cudaGetSymbolAddress((void**)&wtq, g_Wq);
    cudaGetSymbolAddress((void**)&wtk, g_Wk);
    cudaGetSymbolAddress((void**)&wtv, g_Wv);
    cudaGetSymbolAddress((void**)&wto, g_Wo);
    cudaGetSymbolAddress((void**)&qh,  g_Qh);
    cudaGetSymbolAddress((void**)&kh,  g_Kh);
    cudaGetSymbolAddress((void**)&kl,  g_Kl);
    cudaGetSymbolAddress((void**)&vh,  g_Vh);
    cudaGetSymbolAddress((void**)&oh,  g_Oh);
    cudaGetSymbolAddress((void**)&ol,  g_Ol);

    cudaFuncSetAttribute(gemm_qkv,
                         cudaFuncAttributeMaxDynamicSharedMemorySize, HSMEM);
    cudaFuncSetAttribute(gemm_o,
                         cudaFuncAttributeMaxDynamicSharedMemorySize, HSMEM);
    cudaFuncSetAttribute(attn_hmma,
                         cudaFuncAttributeMaxDynamicSharedMemorySize, ATT_SMEM);

    const int n4 = MROWS * Dm / 4;
    dim3 gt(Dm / 32, Dm / 32, 4);
    dim3 gqkv(Dm / 256, MROWS / 128, 3);   // (4, 64, 3)
    dim3 go(Dm / 256, MROWS / 128);        // (4, 64)

    fsplit<<<(n4 + 255) / 256, 256>>>((const float4*)x, (uint2*)ahi, (uint2*)alo, n4);
    wt4_split<<<gt, 256>>>(wq, wk, wv, wo, wtq, wtk, wtv, wto);

    gemm_qkv<<<gqkv, 512, HSMEM>>>(ahi, alo, wtq, wtk, wtv, bq, bk, bv,
                                   qh, kh, kl, vh);

    dim3 ga(Sq / 128, Bsz * Hn);           // (16, 64)
    attn_hmma<<<ga, 256, ATT_SMEM>>>(qh, kh, kl, vh, oh, ol);

    gemm_o<<<go, 512, HSMEM>>>(oh, ol, wto, bo, out);
}